// round 12
// baseline (speedup 1.0000x reference)
#include <cuda_runtime.h>
#include <cuda_bf16.h>
#include <cstdint>
#include <math.h>

#define LSEQ 512
#define HDIM 512
#define NSEQ 64
#define NSTREAM 128
#define GRU2_BLOCKS 128

// ---- scratch (device globals) ----
__device__ __nv_bfloat16 g_Ah[(size_t)NSEQ * LSEQ * 832];   // input hi
__device__ __nv_bfloat16 g_Al[(size_t)NSEQ * LSEQ * 832];   // input lo
__device__ __nv_bfloat16 g_Bh[(size_t)3072 * 832];          // wih hi
__device__ __nv_bfloat16 g_Bl[(size_t)3072 * 832];          // wih lo
__device__ float g_GI[(size_t)NSEQ * LSEQ * 3072];
__device__ __nv_bfloat16 g_Hh[NSTREAM * HDIM];              // hidden hi
__device__ __nv_bfloat16 g_Hl[NSTREAM * HDIM];              // hidden lo
__device__ float g_ENC[(size_t)NSEQ * LSEQ * 1024];
__device__ float g_N[NSEQ * LSEQ];
__device__ float g_SIM[(size_t)32 * LSEQ * LSEQ];
__device__ float g_MS1[32 * LSEQ], g_RL1[32 * LSEQ];
__device__ float g_MS2[32 * LSEQ], g_RL2[32 * LSEQ];
__device__ float g_FEAT[32 * 768];
__device__ unsigned g_bar_cnt;
__device__ unsigned g_bar_gen;

// ---- K1: pack [word | pinyin | pe(l) | pe(tb) | pe(te) | pe(te-l) | pe(l-tb)] as bf16 hi/lo ----
__global__ void embed_pack(const int* __restrict__ w0, const int* __restrict__ w1,
                           const int* __restrict__ py0, const int* __restrict__ py1,
                           const int* __restrict__ tb0, const int* __restrict__ te0,
                           const int* __restrict__ tb1, const int* __restrict__ te1,
                           const float* __restrict__ ew, const float* __restrict__ ep,
                           const float* __restrict__ pe) {
    int seq = blockIdx.x, l = blockIdx.y;
    int side = seq >> 5, b = seq & 31;
    int widx = (side ? w1 : w0)[b * 512 + l];
    int pidx = (side ? py1 : py0)[b * 512 + l];
    int tb = (side ? tb1 : tb0)[b * 512 + l];
    int te = (side ? te1 : te0)[b * 512 + l];
    for (int c = threadIdx.x; c < 832; c += 128) {
        float x;
        if (c < 256) x = ew[(size_t)widx * 256 + c];
        else if (c < 512) x = ep[(size_t)pidx * 256 + (c - 256)];
        else {
            int slot = (c - 512) >> 6, kk = (c - 512) & 63;
            int idx = (slot == 0) ? l : (slot == 1) ? tb : (slot == 2) ? te
                      : (slot == 3) ? (te - l) : (l - tb);
            x = pe[idx * 64 + kk];
        }
        __nv_bfloat16 hi = __float2bfloat16(x);
        __nv_bfloat16 lo = __float2bfloat16(x - __bfloat162float(hi));
        size_t o = (size_t)(seq * 512 + l) * 832 + c;
        g_Ah[o] = hi;
        g_Al[o] = lo;
    }
}

// ---- K1b: split wih into bf16 hi/lo ----
__global__ void wconv(const float* __restrict__ wih) {
    int i = blockIdx.x * 256 + threadIdx.x;
    if (i < 3072 * 832) {
        float x = wih[i];
        __nv_bfloat16 hi = __float2bfloat16(x);
        __nv_bfloat16 lo = __float2bfloat16(x - __bfloat162float(hi));
        g_Bh[i] = hi;
        g_Bl[i] = lo;
    }
}

#define MMA_BF16(d, a, b0v, b1v)                                             \
    asm volatile("mma.sync.aligned.m16n8k16.row.col.f32.bf16.bf16.f32 "      \
                 "{%0,%1,%2,%3}, {%4,%5,%6,%7}, {%8,%9}, {%0,%1,%2,%3};"     \
                 : "+f"(d[0]), "+f"(d[1]), "+f"(d[2]), "+f"(d[3])            \
                 : "r"(a[0]), "r"(a[1]), "r"(a[2]), "r"(a[3]),               \
                   "r"(b0v), "r"(b1v));

// ---- K2: GI = X @ Wih^T + bih  via bf16-split mma.  M=32768 N=3072 K=832 ----
__global__ __launch_bounds__(256) void gemm_gi_mma(const float* __restrict__ bih) {
    __shared__ __align__(16) __nv_bfloat16 Ah[128][40];
    __shared__ __align__(16) __nv_bfloat16 Al[128][40];
    __shared__ __align__(16) __nv_bfloat16 Bh[128][40];
    __shared__ __align__(16) __nv_bfloat16 Bl[128][40];
    int tid = threadIdx.x;
    int n0 = blockIdx.x * 128, m0 = blockIdx.y * 128;
    int wid = tid >> 5, lane = tid & 31;
    int grp = lane >> 2, qp2 = (lane & 3) * 2;
    int wm = (wid >> 2) * 64, wn = (wid & 3) * 32;
    float acc[4][4][4];
#pragma unroll
    for (int i = 0; i < 4; i++)
#pragma unroll
        for (int j = 0; j < 4; j++)
#pragma unroll
            for (int q = 0; q < 4; q++) acc[i][j][q] = 0.f;

    for (int c = 0; c < 26; c++) {
        int k0 = c * 32;
        __syncthreads();
#pragma unroll
        for (int p = 0; p < 2; p++) {
            int t2 = tid + p * 256;
            int row = t2 >> 2, kc = (t2 & 3) * 8;
            *(uint4*)&Ah[row][kc] = *(const uint4*)(g_Ah + (size_t)(m0 + row) * 832 + k0 + kc);
            *(uint4*)&Al[row][kc] = *(const uint4*)(g_Al + (size_t)(m0 + row) * 832 + k0 + kc);
            *(uint4*)&Bh[row][kc] = *(const uint4*)(g_Bh + (size_t)(n0 + row) * 832 + k0 + kc);
            *(uint4*)&Bl[row][kc] = *(const uint4*)(g_Bl + (size_t)(n0 + row) * 832 + k0 + kc);
        }
        __syncthreads();
#pragma unroll
        for (int kk = 0; kk < 32; kk += 16) {
            uint32_t ah[4][4], al[4][4];
#pragma unroll
            for (int i = 0; i < 4; i++) {
                int r = wm + i * 16 + grp;
                ah[i][0] = *(uint32_t*)&Ah[r][kk + qp2];
                ah[i][1] = *(uint32_t*)&Ah[r + 8][kk + qp2];
                ah[i][2] = *(uint32_t*)&Ah[r][kk + 8 + qp2];
                ah[i][3] = *(uint32_t*)&Ah[r + 8][kk + 8 + qp2];
                al[i][0] = *(uint32_t*)&Al[r][kk + qp2];
                al[i][1] = *(uint32_t*)&Al[r + 8][kk + qp2];
                al[i][2] = *(uint32_t*)&Al[r][kk + 8 + qp2];
                al[i][3] = *(uint32_t*)&Al[r + 8][kk + 8 + qp2];
            }
#pragma unroll
            for (int j = 0; j < 4; j++) {
                int nr = wn + j * 8 + grp;
                uint32_t bh0 = *(uint32_t*)&Bh[nr][kk + qp2];
                uint32_t bh1 = *(uint32_t*)&Bh[nr][kk + 8 + qp2];
                uint32_t bl0 = *(uint32_t*)&Bl[nr][kk + qp2];
                uint32_t bl1 = *(uint32_t*)&Bl[nr][kk + 8 + qp2];
#pragma unroll
                for (int i = 0; i < 4; i++) {
                    MMA_BF16(acc[i][j], ah[i], bh0, bh1);
                    MMA_BF16(acc[i][j], ah[i], bl0, bl1);
                    MMA_BF16(acc[i][j], al[i], bh0, bh1);
                }
            }
        }
    }
#pragma unroll
    for (int i = 0; i < 4; i++) {
        int r0 = m0 + wm + i * 16 + grp;
#pragma unroll
        for (int j = 0; j < 4; j++) {
            int cidx = n0 + wn + j * 8 + qp2;
            float2 bb = *(const float2*)&bih[cidx];
            float2 v0 = make_float2(acc[i][j][0] + bb.x, acc[i][j][1] + bb.y);
            float2 v1 = make_float2(acc[i][j][2] + bb.x, acc[i][j][3] + bb.y);
            *(float2*)&g_GI[(size_t)r0 * 3072 + cidx] = v0;
            *(float2*)&g_GI[(size_t)(r0 + 8) * 3072 + cidx] = v1;
        }
    }
}

// ---- flat grid barrier for 128 co-resident blocks ----
__device__ __forceinline__ void grid_bar2() {
    __syncthreads();
    if (threadIdx.x == 0) {
        __threadfence();
        unsigned gen = *(volatile unsigned*)&g_bar_gen;
        if (atomicAdd(&g_bar_cnt, 1u) == GRU2_BLOCKS - 1u) {
            atomicExch(&g_bar_cnt, 0u);
            __threadfence();
            atomicExch(&g_bar_gen, gen + 1u);
        } else {
            while (*(volatile unsigned*)&g_bar_gen == gen) { }
        }
        __threadfence();
    }
    __syncthreads();
}

// ---- K3: persistent bidirectional GRU, tensor-core matvec, ONE barrier/step ----
// 128 blocks x 128 thr. Block = (dir d, hidden-column tile j0..j0+7).
// Computes gh rows {j,512+j,1024+j} for all 64 streams of dir, full K=512, then
// the complete gate update for those (s,j) in-block. fp32 H state is block-local.
__global__ __launch_bounds__(128) void gru_persist2(
    const float* __restrict__ Whh, const float* __restrict__ bhh,
    const int* __restrict__ len1, const int* __restrict__ len2) {
    extern __shared__ __align__(16) unsigned char smem_raw[];
    __nv_bfloat16* Wsh = (__nv_bfloat16*)smem_raw;          // [24][520]
    __nv_bfloat16* Wsl = Wsh + 24 * 520;                    // [24][520]
    __nv_bfloat16* Hsh = Wsl + 24 * 520;                    // [64][520]
    __nv_bfloat16* Hsl = Hsh + 64 * 520;                    // [64][520]
    float* ghs  = (float*)(Hsl + 64 * 520);                 // [64][26]
    float* Hown = ghs + 64 * 26;                            // [64][8]
    float* bhs  = Hown + 64 * 8;                            // [24]

    int bx = blockIdx.x, tid = threadIdx.x;
    int d = bx >> 6, jt = bx & 63, j0 = jt * 8;
    int wid = tid >> 5, lane = tid & 31;
    int grp = lane >> 2, qp2 = (lane & 3) * 2;

    // one-time Whh tile (24 rows: gate g, col j0+jl -> row g*512+j0+jl), bf16 hi/lo
    for (int i = tid; i < 24 * 512; i += 128) {
        int n = i >> 9, k = i & 511;
        int row = (n >> 3) * 512 + j0 + (n & 7);
        float x = Whh[((size_t)d * 1536 + row) * 512 + k];
        __nv_bfloat16 hi = __float2bfloat16(x);
        Wsh[n * 520 + k] = hi;
        Wsl[n * 520 + k] = __float2bfloat16(x - __bfloat162float(hi));
    }
    if (tid < 24) bhs[tid] = bhh[d * 1536 + (tid >> 3) * 512 + j0 + (tid & 7)];
    // zero local H and owned global H slice
    for (int i = tid; i < 64 * 8; i += 128) {
        int s = i >> 3, jl = i & 7;
        Hown[s * 8 + jl] = 0.f;
        g_Hh[(d * 64 + s) * 512 + j0 + jl] = __float2bfloat16(0.f);
        g_Hl[(d * 64 + s) * 512 + j0 + jl] = __float2bfloat16(0.f);
    }
    grid_bar2();

    int r = wid * 16 + grp;
    const __nv_bfloat16* Ha = Hsh + r * 520;
    const __nv_bfloat16* Hb = Hsh + (r + 8) * 520;
    const __nv_bfloat16* La = Hsl + r * 520;
    const __nv_bfloat16* Lb = Hsl + (r + 8) * 520;

    for (int t = 0; t < LSEQ; t++) {
        // load full H slice of this dir into smem (hi+lo), high MLP
        {
            const uint4* srcH = (const uint4*)(g_Hh + (size_t)d * 64 * 512);
            const uint4* srcL = (const uint4*)(g_Hl + (size_t)d * 64 * 512);
            for (int i = tid; i < 64 * 64; i += 128) {
                int rr = i >> 6, kq = i & 63;
                ((uint4*)(Hsh + rr * 520))[kq] = srcH[rr * 64 + kq];
                ((uint4*)(Hsl + rr * 520))[kq] = srcL[rr * 64 + kq];
            }
        }
        __syncthreads();

        // phase A: gh = H @ Wtile^T (3-term bf16 split), warp owns m-tile=wid, all 3 n-tiles
        float acc[3][4];
#pragma unroll
        for (int nt = 0; nt < 3; nt++)
#pragma unroll
            for (int q = 0; q < 4; q++) acc[nt][q] = 0.f;
#pragma unroll 4
        for (int kk = 0; kk < 512; kk += 16) {
            uint32_t ah[4], al[4];
            ah[0] = *(const uint32_t*)(Ha + kk + qp2);
            ah[1] = *(const uint32_t*)(Hb + kk + qp2);
            ah[2] = *(const uint32_t*)(Ha + kk + 8 + qp2);
            ah[3] = *(const uint32_t*)(Hb + kk + 8 + qp2);
            al[0] = *(const uint32_t*)(La + kk + qp2);
            al[1] = *(const uint32_t*)(Lb + kk + qp2);
            al[2] = *(const uint32_t*)(La + kk + 8 + qp2);
            al[3] = *(const uint32_t*)(Lb + kk + 8 + qp2);
#pragma unroll
            for (int nt = 0; nt < 3; nt++) {
                const __nv_bfloat16* Wr = Wsh + (nt * 8 + grp) * 520 + kk;
                const __nv_bfloat16* Wx = Wsl + (nt * 8 + grp) * 520 + kk;
                uint32_t bh0 = *(const uint32_t*)(Wr + qp2);
                uint32_t bh1 = *(const uint32_t*)(Wr + 8 + qp2);
                uint32_t bl0 = *(const uint32_t*)(Wx + qp2);
                uint32_t bl1 = *(const uint32_t*)(Wx + 8 + qp2);
                MMA_BF16(acc[nt], ah, bh0, bh1);
                MMA_BF16(acc[nt], ah, bl0, bl1);
                MMA_BF16(acc[nt], al, bh0, bh1);
            }
        }
        // stage gh to smem
#pragma unroll
        for (int nt = 0; nt < 3; nt++) {
            ghs[r * 26 + nt * 8 + qp2]           = acc[nt][0];
            ghs[r * 26 + nt * 8 + qp2 + 1]       = acc[nt][1];
            ghs[(r + 8) * 26 + nt * 8 + qp2]     = acc[nt][2];
            ghs[(r + 8) * 26 + nt * 8 + qp2 + 1] = acc[nt][3];
        }
        __syncthreads();

        // phase B: gates + state update + output for (64 streams x 8 cols)
        for (int i = tid; i < 512; i += 128) {
            int sl = i >> 3, jl = i & 7;
            int side = sl >> 5, b = sl & 31;
            int len = side ? len2[b] : len1[b];
            bool valid = (t < len);
            int lp = (d == 1 && valid) ? (len - 1 - t) : t;
            int j = j0 + jl;
            const float* gi = g_GI + ((size_t)(sl * 512 + lp)) * 3072 + d * 1536;
            float ghr = ghs[sl * 26 + jl]      + bhs[jl];
            float ghz = ghs[sl * 26 + 8 + jl]  + bhs[8 + jl];
            float ghn = ghs[sl * 26 + 16 + jl] + bhs[16 + jl];
            float h = Hown[sl * 8 + jl];
            float rg = 1.f / (1.f + expf(-(gi[j] + ghr)));
            float zg = 1.f / (1.f + expf(-(gi[512 + j] + ghz)));
            float ng = tanhf(gi[1024 + j] + rg * ghn);
            float hnew = (1.f - zg) * ng + zg * h;
            float hout = valid ? hnew : h;
            Hown[sl * 8 + jl] = hout;
            __nv_bfloat16 hi = __float2bfloat16(hout);
            g_Hh[(d * 64 + sl) * 512 + j] = hi;
            g_Hl[(d * 64 + sl) * 512 + j] = __float2bfloat16(hout - __bfloat162float(hi));
            g_ENC[((size_t)(sl * 512 + lp)) * 1024 + d * 512 + j] = valid ? hnew : 0.f;
        }
        grid_bar2();
    }
}

// ---- K4: row norms ----
__global__ void norms_kernel() {
    int seq = blockIdx.x;
    int w = threadIdx.x >> 5, lane = threadIdx.x & 31;
    int i = blockIdx.y * 8 + w;
    const float* row = g_ENC + ((size_t)seq * 512 + i) * 1024;
    float sacc = 0.f;
    for (int k = lane; k < 1024; k += 32) { float v = row[k]; sacc += v * v; }
#pragma unroll
    for (int off = 16; off; off >>= 1) sacc += __shfl_down_sync(0xffffffffu, sacc, off);
    if (lane == 0) g_N[seq * 512 + i] = sqrtf(sacc);
}

// ---- K5: SIM[b] = enc1[b] @ enc2[b]^T / max(n1*n2, eps) ----
__global__ __launch_bounds__(256) void sim_gemm() {
    int b = blockIdx.z;
    int n0 = blockIdx.x * 128, m0 = blockIdx.y * 128;
    __shared__ float As[16][132];
    __shared__ float Bs[16][132];
    const float* A = g_ENC + ((size_t)b * 512 + m0) * 1024;
    const float* Bp = g_ENC + ((size_t)(32 + b) * 512 + n0) * 1024;
    int tid = threadIdx.x;
    int tx = tid % 16, ty = tid / 16;
    int lr = tid >> 2, lc = (tid & 3) << 2;
    float acc[8][8];
#pragma unroll
    for (int i = 0; i < 8; i++)
#pragma unroll
        for (int j = 0; j < 8; j++) acc[i][j] = 0.f;
    for (int kc = 0; kc < 64; kc++) {
        int K0 = kc * 16;
        float4 ra0 = *(const float4*)(A + (size_t)lr * 1024 + K0 + lc);
        float4 ra1 = *(const float4*)(A + (size_t)(lr + 64) * 1024 + K0 + lc);
        float4 rb0 = *(const float4*)(Bp + (size_t)lr * 1024 + K0 + lc);
        float4 rb1 = *(const float4*)(Bp + (size_t)(lr + 64) * 1024 + K0 + lc);
        __syncthreads();
        As[lc+0][lr]=ra0.x; As[lc+1][lr]=ra0.y; As[lc+2][lr]=ra0.z; As[lc+3][lr]=ra0.w;
        As[lc+0][lr+64]=ra1.x; As[lc+1][lr+64]=ra1.y; As[lc+2][lr+64]=ra1.z; As[lc+3][lr+64]=ra1.w;
        Bs[lc+0][lr]=rb0.x; Bs[lc+1][lr]=rb0.y; Bs[lc+2][lr]=rb0.z; Bs[lc+3][lr]=rb0.w;
        Bs[lc+0][lr+64]=rb1.x; Bs[lc+1][lr+64]=rb1.y; Bs[lc+2][lr+64]=rb1.z; Bs[lc+3][lr+64]=rb1.w;
        __syncthreads();
#pragma unroll
        for (int kk = 0; kk < 16; kk++) {
            float4 a0 = *(const float4*)&As[kk][ty * 8];
            float4 a1 = *(const float4*)&As[kk][ty * 8 + 4];
            float4 b0 = *(const float4*)&Bs[kk][tx * 8];
            float4 b1 = *(const float4*)&Bs[kk][tx * 8 + 4];
            float av[8] = {a0.x,a0.y,a0.z,a0.w,a1.x,a1.y,a1.z,a1.w};
            float bv[8] = {b0.x,b0.y,b0.z,b0.w,b1.x,b1.y,b1.z,b1.w};
#pragma unroll
            for (int i = 0; i < 8; i++)
#pragma unroll
                for (int j = 0; j < 8; j++) acc[i][j] += av[i] * bv[j];
        }
    }
#pragma unroll
    for (int i = 0; i < 8; i++) {
        int row = m0 + ty * 8 + i;
        float n1 = g_N[b * 512 + row];
        float* dst = g_SIM + ((size_t)b * 512 + row) * 512 + n0 + tx * 8;
#pragma unroll
        for (int j = 0; j < 8; j++) {
            float n2 = g_N[(32 + b) * 512 + n0 + tx * 8 + j];
            dst[j] = acc[i][j] / fmaxf(n1 * n2, 1e-8f);
        }
    }
}

// ---- K6: max/argmax over axis 2 ----
__global__ void rowmax_kernel() {
    int b = blockIdx.x;
    int w = threadIdx.x >> 5, lane = threadIdx.x & 31;
    int i = blockIdx.y * 8 + w;
    const float* row = g_SIM + ((size_t)b * 512 + i) * 512;
    float best = -1e30f; int bi = 0;
    for (int j = lane; j < 512; j += 32) {
        float v = row[j];
        if (v > best) { best = v; bi = j; }
    }
#pragma unroll
    for (int off = 16; off; off >>= 1) {
        float v = __shfl_down_sync(0xffffffffu, best, off);
        int ii = __shfl_down_sync(0xffffffffu, bi, off);
        if (v > best || (v == best && ii < bi)) { best = v; bi = ii; }
    }
    if (lane == 0) {
        g_MS1[b * 512 + i] = best;
        g_RL1[b * 512 + i] = (float)(i - bi);
    }
}

// ---- K7: max/argmax over axis 1 ----
__global__ void colmax_kernel() {
    int b = blockIdx.x, j0 = blockIdx.y * 32;
    int g = threadIdx.x >> 5, j = threadIdx.x & 31;
    float best = -1e30f; int bi = 0;
    const float* S = g_SIM + (size_t)b * 512 * 512;
    for (int i = g; i < 512; i += 8) {
        float v = S[(size_t)i * 512 + j0 + j];
        if (v > best) { best = v; bi = i; }
    }
    __shared__ float sm[256];
    __shared__ int si[256];
    sm[threadIdx.x] = best; si[threadIdx.x] = bi;
    __syncthreads();
    if (g == 0) {
        for (int gg = 1; gg < 8; gg++) {
            float v = sm[gg * 32 + j]; int ii = si[gg * 32 + j];
            if (v > best || (v == best && ii < bi)) { best = v; bi = ii; }
        }
        int jj = j0 + j;
        g_MS2[b * 512 + jj] = best;
        g_RL2[b * 512 + jj] = (float)(jj - bi);
    }
}

// ---- K8: conv branches + BN + ReLU + maxpool ----
__global__ void branch_kernel(const float* __restrict__ cw0, const float* __restrict__ cw1,
                              const float* __restrict__ cw2, const float* __restrict__ cb,
                              const float* __restrict__ bng, const float* __restrict__ bnb,
                              const float* __restrict__ bnm, const float* __restrict__ bnv) {
    int b = blockIdx.x, br = blockIdx.y;
    __shared__ float xs[2][512];
    const float* ms = br ? g_MS2 : g_MS1;
    const float* rl = br ? g_RL2 : g_RL1;
    for (int i = threadIdx.x; i < 512; i += 384) {
        xs[0][i] = ms[b * 512 + i];
        xs[1][i] = rl[b * 512 + i];
    }
    __syncthreads();
    int t = threadIdx.x;
    int ci = t >> 7, o = t & 127;
    int ks = 2 + ci;
    const float* w = (ci == 0) ? cw0 : ((ci == 1) ? cw1 : cw2);
    float wreg[2][4];
    for (int c = 0; c < 2; c++)
        for (int q = 0; q < 4; q++) wreg[c][q] = (q < ks) ? w[(o * 2 + c) * ks + q] : 0.f;
    float bias = cb[ci * 128 + o];
    float inv = rsqrtf(bnv[ci * 128 + o] + 1e-5f);
    float sc = bng[ci * 128 + o] * inv;
    float sh = bnb[ci * 128 + o] + (bias - bnm[ci * 128 + o]) * sc;
    float best = -1e30f;
    int P = 512 - ks + 1;
    for (int p = 0; p < P; p++) {
        float v = 0.f;
        for (int q = 0; q < ks; q++) {
            v += wreg[0][q] * xs[0][p + q];
            v += wreg[1][q] * xs[1][p + q];
        }
        v = fmaxf(v * sc + sh, 0.f);
        best = fmaxf(best, v);
    }
    g_FEAT[b * 768 + br * 384 + ci * 128 + o] = best;
}

// ---- K9: fc + softmax ----
__global__ void fc_kernel(const float* __restrict__ fw, const float* __restrict__ fb,
                          float* __restrict__ out) {
    int b = blockIdx.x;
    int w = threadIdx.x >> 5, lane = threadIdx.x & 31;
    __shared__ float lg[2];
    if (w < 2) {
        float s = 0.f;
        for (int k = lane; k < 768; k += 32) s += fw[w * 768 + k] * g_FEAT[b * 768 + k];
#pragma unroll
        for (int off = 16; off; off >>= 1) s += __shfl_down_sync(0xffffffffu, s, off);
        if (lane == 0) lg[w] = s + fb[w];
    }
    __syncthreads();
    if (threadIdx.x == 0) {
        float m = fmaxf(lg[0], lg[1]);
        float e0 = expf(lg[0] - m), e1 = expf(lg[1] - m);
        float inv = 1.f / (e0 + e1);
        out[b * 2 + 0] = e0 * inv;
        out[b * 2 + 1] = e1 * inv;
    }
}

extern "C" void kernel_launch(void* const* d_in, const int* in_sizes, int n_in,
                              void* d_out, int out_size) {
    const int* word1 = (const int*)d_in[0];
    const int* word2 = (const int*)d_in[1];
    const int* piny1 = (const int*)d_in[2];
    const int* piny2 = (const int*)d_in[3];
    const int* len1  = (const int*)d_in[4];
    const int* len2  = (const int*)d_in[5];
    const int* tb1   = (const int*)d_in[6];
    const int* te1   = (const int*)d_in[7];
    const int* tb2   = (const int*)d_in[8];
    const int* te2   = (const int*)d_in[9];
    const float* ew  = (const float*)d_in[10];
    const float* ep  = (const float*)d_in[11];
    const float* pe  = (const float*)d_in[12];
    const float* wih = (const float*)d_in[13];
    const float* whh = (const float*)d_in[14];
    const float* bih = (const float*)d_in[15];
    const float* bhh = (const float*)d_in[16];
    const float* cw0 = (const float*)d_in[17];
    const float* cw1 = (const float*)d_in[18];
    const float* cw2 = (const float*)d_in[19];
    const float* cb  = (const float*)d_in[20];
    const float* bng = (const float*)d_in[21];
    const float* bnb = (const float*)d_in[22];
    const float* bnm = (const float*)d_in[23];
    const float* bnv = (const float*)d_in[24];
    const float* fw  = (const float*)d_in[25];
    const float* fb  = (const float*)d_in[26];
    float* out = (float*)d_out;

    // dynamic smem for the persistent GRU: Wsh/Wsl 24x520, Hsh/Hsl 64x520 (bf16),
    // ghs 64x26 f32, Hown 64x8 f32, bhs 24 f32
    const int GRU2_SMEM = (24*520*2 + 64*520*2) * 2 + 64*26*4 + 64*8*4 + 24*4;
    cudaFuncSetAttribute(gru_persist2, cudaFuncAttributeMaxDynamicSharedMemorySize, GRU2_SMEM);

    wconv<<<9984, 256>>>(wih);
    embed_pack<<<dim3(64, 512), 128>>>(word1, word2, piny1, piny2,
                                       tb1, te1, tb2, te2, ew, ep, pe);
    gemm_gi_mma<<<dim3(24, 256), 256>>>(bih);
    gru_persist2<<<GRU2_BLOCKS, 128, GRU2_SMEM>>>(whh, bhh, len1, len2);
    norms_kernel<<<dim3(64, 64), 256>>>();
    sim_gemm<<<dim3(4, 4, 32), 256>>>();
    rowmax_kernel<<<dim3(32, 64), 256>>>();
    colmax_kernel<<<dim3(32, 16), 256>>>();
    branch_kernel<<<dim3(32, 2), 384>>>(cw0, cw1, cw2, cb, bng, bnb, bnm, bnv);
    fc_kernel<<<32, 64>>>(fw, fb, out);
}

// round 13
// speedup vs baseline: 2.0200x; 2.0200x over previous
#include <cuda_runtime.h>
#include <cuda_bf16.h>
#include <cstdint>
#include <math.h>

#define LSEQ 512
#define HDIM 512
#define NSEQ 64
#define NSTREAM 128

// ---- scratch (device globals) ----
__device__ __nv_bfloat16 g_Ah[(size_t)NSEQ * LSEQ * 832];   // input hi
__device__ __nv_bfloat16 g_Al[(size_t)NSEQ * LSEQ * 832];   // input lo
__device__ __nv_bfloat16 g_Bh[(size_t)3072 * 832];          // wih hi
__device__ __nv_bfloat16 g_Bl[(size_t)3072 * 832];          // wih lo
__device__ float g_GI[(size_t)NSEQ * LSEQ * 3072];
__device__ __nv_bfloat16 g_Hh[2][NSTREAM * HDIM];           // hidden hi (ping-pong)
__device__ __nv_bfloat16 g_Hl[2][NSTREAM * HDIM];           // hidden lo (ping-pong)
__device__ float g_ENC[(size_t)NSEQ * LSEQ * 1024];
__device__ float g_N[NSEQ * LSEQ];
__device__ float g_SIM[(size_t)32 * LSEQ * LSEQ];
__device__ float g_MS1[32 * LSEQ], g_RL1[32 * LSEQ];
__device__ float g_MS2[32 * LSEQ], g_RL2[32 * LSEQ];
__device__ float g_FEAT[32 * 768];
__device__ unsigned g_bar_ctr[2 * 32];                      // per-dir monotonic, 128B apart

__global__ void zero_bar() {
    g_bar_ctr[0] = 0u;
    g_bar_ctr[32] = 0u;
}

// ---- K1: pack [word | pinyin | pe(l) | pe(tb) | pe(te) | pe(te-l) | pe(l-tb)] as bf16 hi/lo ----
__global__ void embed_pack(const int* __restrict__ w0, const int* __restrict__ w1,
                           const int* __restrict__ py0, const int* __restrict__ py1,
                           const int* __restrict__ tb0, const int* __restrict__ te0,
                           const int* __restrict__ tb1, const int* __restrict__ te1,
                           const float* __restrict__ ew, const float* __restrict__ ep,
                           const float* __restrict__ pe) {
    int seq = blockIdx.x, l = blockIdx.y;
    int side = seq >> 5, b = seq & 31;
    int widx = (side ? w1 : w0)[b * 512 + l];
    int pidx = (side ? py1 : py0)[b * 512 + l];
    int tb = (side ? tb1 : tb0)[b * 512 + l];
    int te = (side ? te1 : te0)[b * 512 + l];
    for (int c = threadIdx.x; c < 832; c += 128) {
        float x;
        if (c < 256) x = ew[(size_t)widx * 256 + c];
        else if (c < 512) x = ep[(size_t)pidx * 256 + (c - 256)];
        else {
            int slot = (c - 512) >> 6, kk = (c - 512) & 63;
            int idx = (slot == 0) ? l : (slot == 1) ? tb : (slot == 2) ? te
                      : (slot == 3) ? (te - l) : (l - tb);
            x = pe[idx * 64 + kk];
        }
        __nv_bfloat16 hi = __float2bfloat16(x);
        __nv_bfloat16 lo = __float2bfloat16(x - __bfloat162float(hi));
        size_t o = (size_t)(seq * 512 + l) * 832 + c;
        g_Ah[o] = hi;
        g_Al[o] = lo;
    }
}

// ---- K1b: split wih into bf16 hi/lo ----
__global__ void wconv(const float* __restrict__ wih) {
    int i = blockIdx.x * 256 + threadIdx.x;
    if (i < 3072 * 832) {
        float x = wih[i];
        __nv_bfloat16 hi = __float2bfloat16(x);
        __nv_bfloat16 lo = __float2bfloat16(x - __bfloat162float(hi));
        g_Bh[i] = hi;
        g_Bl[i] = lo;
    }
}

#define MMA_BF16(d, a, b0v, b1v)                                             \
    asm volatile("mma.sync.aligned.m16n8k16.row.col.f32.bf16.bf16.f32 "      \
                 "{%0,%1,%2,%3}, {%4,%5,%6,%7}, {%8,%9}, {%0,%1,%2,%3};"     \
                 : "+f"(d[0]), "+f"(d[1]), "+f"(d[2]), "+f"(d[3])            \
                 : "r"(a[0]), "r"(a[1]), "r"(a[2]), "r"(a[3]),               \
                   "r"(b0v), "r"(b1v));

// ---- K2: GI = X @ Wih^T + bih  via bf16-split mma.  M=32768 N=3072 K=832 ----
__global__ __launch_bounds__(256) void gemm_gi_mma(const float* __restrict__ bih) {
    __shared__ __align__(16) __nv_bfloat16 Ah[128][40];
    __shared__ __align__(16) __nv_bfloat16 Al[128][40];
    __shared__ __align__(16) __nv_bfloat16 Bh[128][40];
    __shared__ __align__(16) __nv_bfloat16 Bl[128][40];
    int tid = threadIdx.x;
    int n0 = blockIdx.x * 128, m0 = blockIdx.y * 128;
    int wid = tid >> 5, lane = tid & 31;
    int grp = lane >> 2, qp2 = (lane & 3) * 2;
    int wm = (wid >> 2) * 64, wn = (wid & 3) * 32;
    float acc[4][4][4];
#pragma unroll
    for (int i = 0; i < 4; i++)
#pragma unroll
        for (int j = 0; j < 4; j++)
#pragma unroll
            for (int q = 0; q < 4; q++) acc[i][j][q] = 0.f;

    for (int c = 0; c < 26; c++) {
        int k0 = c * 32;
        __syncthreads();
#pragma unroll
        for (int p = 0; p < 2; p++) {
            int t2 = tid + p * 256;
            int row = t2 >> 2, kc = (t2 & 3) * 8;
            *(uint4*)&Ah[row][kc] = *(const uint4*)(g_Ah + (size_t)(m0 + row) * 832 + k0 + kc);
            *(uint4*)&Al[row][kc] = *(const uint4*)(g_Al + (size_t)(m0 + row) * 832 + k0 + kc);
            *(uint4*)&Bh[row][kc] = *(const uint4*)(g_Bh + (size_t)(n0 + row) * 832 + k0 + kc);
            *(uint4*)&Bl[row][kc] = *(const uint4*)(g_Bl + (size_t)(n0 + row) * 832 + k0 + kc);
        }
        __syncthreads();
#pragma unroll
        for (int kk = 0; kk < 32; kk += 16) {
            uint32_t ah[4][4], al[4][4];
#pragma unroll
            for (int i = 0; i < 4; i++) {
                int r = wm + i * 16 + grp;
                ah[i][0] = *(uint32_t*)&Ah[r][kk + qp2];
                ah[i][1] = *(uint32_t*)&Ah[r + 8][kk + qp2];
                ah[i][2] = *(uint32_t*)&Ah[r][kk + 8 + qp2];
                ah[i][3] = *(uint32_t*)&Ah[r + 8][kk + 8 + qp2];
                al[i][0] = *(uint32_t*)&Al[r][kk + qp2];
                al[i][1] = *(uint32_t*)&Al[r + 8][kk + qp2];
                al[i][2] = *(uint32_t*)&Al[r][kk + 8 + qp2];
                al[i][3] = *(uint32_t*)&Al[r + 8][kk + 8 + qp2];
            }
#pragma unroll
            for (int j = 0; j < 4; j++) {
                int nr = wn + j * 8 + grp;
                uint32_t bh0 = *(uint32_t*)&Bh[nr][kk + qp2];
                uint32_t bh1 = *(uint32_t*)&Bh[nr][kk + 8 + qp2];
                uint32_t bl0 = *(uint32_t*)&Bl[nr][kk + qp2];
                uint32_t bl1 = *(uint32_t*)&Bl[nr][kk + 8 + qp2];
#pragma unroll
                for (int i = 0; i < 4; i++) {
                    MMA_BF16(acc[i][j], ah[i], bh0, bh1);
                    MMA_BF16(acc[i][j], ah[i], bl0, bl1);
                    MMA_BF16(acc[i][j], al[i], bh0, bh1);
                }
            }
        }
    }
#pragma unroll
    for (int i = 0; i < 4; i++) {
        int r0 = m0 + wm + i * 16 + grp;
#pragma unroll
        for (int j = 0; j < 4; j++) {
            int cidx = n0 + wn + j * 8 + qp2;
            float2 bb = *(const float2*)&bih[cidx];
            float2 v0 = make_float2(acc[i][j][0] + bb.x, acc[i][j][1] + bb.y);
            float2 v1 = make_float2(acc[i][j][2] + bb.x, acc[i][j][3] + bb.y);
            *(float2*)&g_GI[(size_t)r0 * 3072 + cidx] = v0;
            *(float2*)&g_GI[(size_t)(r0 + 8) * 3072 + cidx] = v1;
        }
    }
}

// ---- MMA half-K body for the recurrence ----
__device__ __forceinline__ void mma_khalf(
    const __nv_bfloat16* __restrict__ Hsh, const __nv_bfloat16* __restrict__ Hsl,
    const __nv_bfloat16* __restrict__ Wsh, const __nv_bfloat16* __restrict__ Wsl,
    int r, int grp, int qp2, int k0, int k1, float acc[3][4]) {
    const __nv_bfloat16* Ha = Hsh + r * 520;
    const __nv_bfloat16* Hb = Hsh + (r + 8) * 520;
    const __nv_bfloat16* La = Hsl + r * 520;
    const __nv_bfloat16* Lb = Hsl + (r + 8) * 520;
#pragma unroll 4
    for (int kk = k0; kk < k1; kk += 16) {
        uint32_t ah[4], al[4];
        ah[0] = *(const uint32_t*)(Ha + kk + qp2);
        ah[1] = *(const uint32_t*)(Hb + kk + qp2);
        ah[2] = *(const uint32_t*)(Ha + kk + 8 + qp2);
        ah[3] = *(const uint32_t*)(Hb + kk + 8 + qp2);
        al[0] = *(const uint32_t*)(La + kk + qp2);
        al[1] = *(const uint32_t*)(Lb + kk + qp2);
        al[2] = *(const uint32_t*)(La + kk + 8 + qp2);
        al[3] = *(const uint32_t*)(Lb + kk + 8 + qp2);
#pragma unroll
        for (int nt = 0; nt < 3; nt++) {
            const __nv_bfloat16* Wr = Wsh + (nt * 8 + grp) * 520 + kk;
            const __nv_bfloat16* Wx = Wsl + (nt * 8 + grp) * 520 + kk;
            uint32_t bh0 = *(const uint32_t*)(Wr + qp2);
            uint32_t bh1 = *(const uint32_t*)(Wr + 8 + qp2);
            uint32_t bl0 = *(const uint32_t*)(Wx + qp2);
            uint32_t bl1 = *(const uint32_t*)(Wx + 8 + qp2);
            MMA_BF16(acc[nt], ah, bh0, bh1);
            MMA_BF16(acc[nt], ah, bl0, bl1);
            MMA_BF16(acc[nt], al, bh0, bh1);
        }
    }
}

// ---- K3: persistent bidirectional GRU; pipelined, per-dir barrier, H ping-pong ----
// 128 blocks x 128 thr. Block = (dir d, hidden-col tile j0..j0+7).
__global__ __launch_bounds__(128) void gru_persist3(
    const float* __restrict__ Whh, const float* __restrict__ bhh,
    const int* __restrict__ len1, const int* __restrict__ len2) {
    extern __shared__ __align__(16) unsigned char smem_raw[];
    __nv_bfloat16* Wsh = (__nv_bfloat16*)smem_raw;          // [24][520]
    __nv_bfloat16* Wsl = Wsh + 24 * 520;
    __nv_bfloat16* Hsh = Wsl + 24 * 520;                    // [64][520]
    __nv_bfloat16* Hsl = Hsh + 64 * 520;
    float* ghs = (float*)(Hsl + 64 * 520);                  // [64][26]
    float* bhs = ghs + 64 * 26;                             // [24]

    int bx = blockIdx.x, tid = threadIdx.x;
    int d = bx >> 6, jt = bx & 63, j0 = jt * 8;
    int wid = tid >> 5, lane = tid & 31;
    int grp = lane >> 2, qp2 = (lane & 3) * 2;
    int r = wid * 16 + grp;

    // one-time Whh tile (24 rows: gate g of col j0+jl), bf16 hi/lo
    for (int i = tid; i < 24 * 512; i += 128) {
        int n = i >> 9, k = i & 511;
        int row = (n >> 3) * 512 + j0 + (n & 7);
        float x = Whh[((size_t)d * 1536 + row) * 512 + k];
        __nv_bfloat16 hi = __float2bfloat16(x);
        Wsh[n * 520 + k] = hi;
        Wsl[n * 520 + k] = __float2bfloat16(x - __bfloat162float(hi));
    }
    if (tid < 24) bhs[tid] = bhh[d * 1536 + (tid >> 3) * 512 + j0 + (tid & 7)];

    // per-thread state: 4 (sl, jl) pairs; lens preloaded
    int sl_r[4], jl_r[4], len_r[4];
    float hloc[4];
#pragma unroll
    for (int q = 0; q < 4; q++) {
        int i = tid + q * 128;
        sl_r[q] = i >> 3; jl_r[q] = i & 7;
        int side = sl_r[q] >> 5, b = sl_r[q] & 31;
        len_r[q] = side ? len2[b] : len1[b];
        hloc[q] = 0.f;
        g_Hh[0][(d * 64 + sl_r[q]) * 512 + j0 + jl_r[q]] = __float2bfloat16(0.f);
        g_Hl[0][(d * 64 + sl_r[q]) * 512 + j0 + jl_r[q]] = __float2bfloat16(0.f);
    }
    __syncthreads();
    if (tid == 0) { __threadfence(); atomicAdd(&g_bar_ctr[d * 32], 1u); }

    for (int t = 0; t < LSEQ; t++) {
        // ---- prefetch gi(t) into registers (independent of barrier) ----
        float gpre[4][3]; int lp_r[4]; bool valid_r[4];
#pragma unroll
        for (int q = 0; q < 4; q++) {
            bool valid = (t < len_r[q]);
            int lp = (d == 1 && valid) ? (len_r[q] - 1 - t) : t;
            const float* gi = g_GI + ((size_t)(sl_r[q] * 512 + lp)) * 3072 + d * 1536 + j0 + jl_r[q];
            gpre[q][0] = gi[0]; gpre[q][1] = gi[512]; gpre[q][2] = gi[1024];
            lp_r[q] = lp; valid_r[q] = valid;
        }

        // ---- wait for H(t) published by all 64 blocks of this dir ----
        if (tid == 0) {
            unsigned tgt = 64u * (unsigned)(t + 1);
            volatile unsigned* p = &g_bar_ctr[d * 32];
            int bo = 8;
            while (*p < tgt) { __nanosleep(bo); if (bo < 128) bo += bo; }
            __threadfence();
        }
        __syncthreads();

        // ---- cp.async H (ping buffer t&1), two K-halves ----
        const char* baseH = (const char*)(g_Hh[t & 1] + (size_t)d * 64 * 512);
        const char* baseL = (const char*)(g_Hl[t & 1] + (size_t)d * 64 * 512);
#pragma unroll
        for (int h = 0; h < 2; h++) {
            for (int i = tid; i < 64 * 32; i += 128) {
                int rr = i >> 5, kq = (i & 31) + h * 32;
                unsigned dH = (unsigned)__cvta_generic_to_shared(Hsh + rr * 520) + kq * 16;
                unsigned dL = (unsigned)__cvta_generic_to_shared(Hsl + rr * 520) + kq * 16;
                const char* sH = baseH + (rr * 64 + kq) * 16;
                const char* sL = baseL + (rr * 64 + kq) * 16;
                asm volatile("cp.async.cg.shared.global [%0], [%1], 16;" :: "r"(dH), "l"(sH));
                asm volatile("cp.async.cg.shared.global [%0], [%1], 16;" :: "r"(dL), "l"(sL));
            }
            asm volatile("cp.async.commit_group;");
        }
        float acc[3][4];
#pragma unroll
        for (int nt = 0; nt < 3; nt++)
#pragma unroll
            for (int q = 0; q < 4; q++) acc[nt][q] = 0.f;
        asm volatile("cp.async.wait_group 1;" ::: "memory");
        __syncthreads();
        mma_khalf(Hsh, Hsl, Wsh, Wsl, r, grp, qp2, 0, 256, acc);
        asm volatile("cp.async.wait_group 0;" ::: "memory");
        __syncthreads();
        mma_khalf(Hsh, Hsl, Wsh, Wsl, r, grp, qp2, 256, 512, acc);

        // stage gh to smem
#pragma unroll
        for (int nt = 0; nt < 3; nt++) {
            ghs[r * 26 + nt * 8 + qp2]           = acc[nt][0];
            ghs[r * 26 + nt * 8 + qp2 + 1]       = acc[nt][1];
            ghs[(r + 8) * 26 + nt * 8 + qp2]     = acc[nt][2];
            ghs[(r + 8) * 26 + nt * 8 + qp2 + 1] = acc[nt][3];
        }
        __syncthreads();

        // ---- gates + state update; publish H(t+1) to pong buffer, arrive early ----
        float enc_r[4];
        __nv_bfloat16* outH = g_Hh[(t + 1) & 1] + (size_t)d * 64 * 512;
        __nv_bfloat16* outL = g_Hl[(t + 1) & 1] + (size_t)d * 64 * 512;
#pragma unroll
        for (int q = 0; q < 4; q++) {
            int sl = sl_r[q], jl = jl_r[q];
            float ghr = ghs[sl * 26 + jl]      + bhs[jl];
            float ghz = ghs[sl * 26 + 8 + jl]  + bhs[8 + jl];
            float ghn = ghs[sl * 26 + 16 + jl] + bhs[16 + jl];
            float h = hloc[q];
            float rg = 1.f / (1.f + __expf(-(gpre[q][0] + ghr)));
            float zg = 1.f / (1.f + __expf(-(gpre[q][1] + ghz)));
            float ng = tanhf(gpre[q][2] + rg * ghn);
            float hnew = (1.f - zg) * ng + zg * h;
            float hout = valid_r[q] ? hnew : h;
            hloc[q] = hout;
            __nv_bfloat16 hi = __float2bfloat16(hout);
            outH[sl * 512 + j0 + jl] = hi;
            outL[sl * 512 + j0 + jl] = __float2bfloat16(hout - __bfloat162float(hi));
            enc_r[q] = valid_r[q] ? hnew : 0.f;
        }
        __syncthreads();
        if (tid == 0) { __threadfence(); atomicAdd(&g_bar_ctr[d * 32], 1u); }
        // ENC stores off the critical path
#pragma unroll
        for (int q = 0; q < 4; q++)
            g_ENC[((size_t)(sl_r[q] * 512 + lp_r[q])) * 1024 + d * 512 + j0 + jl_r[q]] = enc_r[q];
    }
}

// ---- K4: row norms ----
__global__ void norms_kernel() {
    int seq = blockIdx.x;
    int w = threadIdx.x >> 5, lane = threadIdx.x & 31;
    int i = blockIdx.y * 8 + w;
    const float* row = g_ENC + ((size_t)seq * 512 + i) * 1024;
    float sacc = 0.f;
    for (int k = lane; k < 1024; k += 32) { float v = row[k]; sacc += v * v; }
#pragma unroll
    for (int off = 16; off; off >>= 1) sacc += __shfl_down_sync(0xffffffffu, sacc, off);
    if (lane == 0) g_N[seq * 512 + i] = sqrtf(sacc);
}

// ---- K5: SIM[b] = enc1[b] @ enc2[b]^T / max(n1*n2, eps) ----
__global__ __launch_bounds__(256) void sim_gemm() {
    int b = blockIdx.z;
    int n0 = blockIdx.x * 128, m0 = blockIdx.y * 128;
    __shared__ float As[16][132];
    __shared__ float Bs[16][132];
    const float* A = g_ENC + ((size_t)b * 512 + m0) * 1024;
    const float* Bp = g_ENC + ((size_t)(32 + b) * 512 + n0) * 1024;
    int tid = threadIdx.x;
    int tx = tid % 16, ty = tid / 16;
    int lr = tid >> 2, lc = (tid & 3) << 2;
    float acc[8][8];
#pragma unroll
    for (int i = 0; i < 8; i++)
#pragma unroll
        for (int j = 0; j < 8; j++) acc[i][j] = 0.f;
    for (int kc = 0; kc < 64; kc++) {
        int K0 = kc * 16;
        float4 ra0 = *(const float4*)(A + (size_t)lr * 1024 + K0 + lc);
        float4 ra1 = *(const float4*)(A + (size_t)(lr + 64) * 1024 + K0 + lc);
        float4 rb0 = *(const float4*)(Bp + (size_t)lr * 1024 + K0 + lc);
        float4 rb1 = *(const float4*)(Bp + (size_t)(lr + 64) * 1024 + K0 + lc);
        __syncthreads();
        As[lc+0][lr]=ra0.x; As[lc+1][lr]=ra0.y; As[lc+2][lr]=ra0.z; As[lc+3][lr]=ra0.w;
        As[lc+0][lr+64]=ra1.x; As[lc+1][lr+64]=ra1.y; As[lc+2][lr+64]=ra1.z; As[lc+3][lr+64]=ra1.w;
        Bs[lc+0][lr]=rb0.x; Bs[lc+1][lr]=rb0.y; Bs[lc+2][lr]=rb0.z; Bs[lc+3][lr]=rb0.w;
        Bs[lc+0][lr+64]=rb1.x; Bs[lc+1][lr+64]=rb1.y; Bs[lc+2][lr+64]=rb1.z; Bs[lc+3][lr+64]=rb1.w;
        __syncthreads();
#pragma unroll
        for (int kk = 0; kk < 16; kk++) {
            float4 a0 = *(const float4*)&As[kk][ty * 8];
            float4 a1 = *(const float4*)&As[kk][ty * 8 + 4];
            float4 b0 = *(const float4*)&Bs[kk][tx * 8];
            float4 b1 = *(const float4*)&Bs[kk][tx * 8 + 4];
            float av[8] = {a0.x,a0.y,a0.z,a0.w,a1.x,a1.y,a1.z,a1.w};
            float bv[8] = {b0.x,b0.y,b0.z,b0.w,b1.x,b1.y,b1.z,b1.w};
#pragma unroll
            for (int i = 0; i < 8; i++)
#pragma unroll
                for (int j = 0; j < 8; j++) acc[i][j] += av[i] * bv[j];
        }
    }
#pragma unroll
    for (int i = 0; i < 8; i++) {
        int row = m0 + ty * 8 + i;
        float n1 = g_N[b * 512 + row];
        float* dst = g_SIM + ((size_t)b * 512 + row) * 512 + n0 + tx * 8;
#pragma unroll
        for (int j = 0; j < 8; j++) {
            float n2 = g_N[(32 + b) * 512 + n0 + tx * 8 + j];
            dst[j] = acc[i][j] / fmaxf(n1 * n2, 1e-8f);
        }
    }
}

// ---- K6: max/argmax over axis 2 ----
__global__ void rowmax_kernel() {
    int b = blockIdx.x;
    int w = threadIdx.x >> 5, lane = threadIdx.x & 31;
    int i = blockIdx.y * 8 + w;
    const float* row = g_SIM + ((size_t)b * 512 + i) * 512;
    float best = -1e30f; int bi = 0;
    for (int j = lane; j < 512; j += 32) {
        float v = row[j];
        if (v > best) { best = v; bi = j; }
    }
#pragma unroll
    for (int off = 16; off; off >>= 1) {
        float v = __shfl_down_sync(0xffffffffu, best, off);
        int ii = __shfl_down_sync(0xffffffffu, bi, off);
        if (v > best || (v == best && ii < bi)) { best = v; bi = ii; }
    }
    if (lane == 0) {
        g_MS1[b * 512 + i] = best;
        g_RL1[b * 512 + i] = (float)(i - bi);
    }
}

// ---- K7: max/argmax over axis 1 ----
__global__ void colmax_kernel() {
    int b = blockIdx.x, j0 = blockIdx.y * 32;
    int g = threadIdx.x >> 5, j = threadIdx.x & 31;
    float best = -1e30f; int bi = 0;
    const float* S = g_SIM + (size_t)b * 512 * 512;
    for (int i = g; i < 512; i += 8) {
        float v = S[(size_t)i * 512 + j0 + j];
        if (v > best) { best = v; bi = i; }
    }
    __shared__ float sm[256];
    __shared__ int si[256];
    sm[threadIdx.x] = best; si[threadIdx.x] = bi;
    __syncthreads();
    if (g == 0) {
        for (int gg = 1; gg < 8; gg++) {
            float v = sm[gg * 32 + j]; int ii = si[gg * 32 + j];
            if (v > best || (v == best && ii < bi)) { best = v; bi = ii; }
        }
        int jj = j0 + j;
        g_MS2[b * 512 + jj] = best;
        g_RL2[b * 512 + jj] = (float)(jj - bi);
    }
}

// ---- K8: conv branches + BN + ReLU + maxpool ----
__global__ void branch_kernel(const float* __restrict__ cw0, const float* __restrict__ cw1,
                              const float* __restrict__ cw2, const float* __restrict__ cb,
                              const float* __restrict__ bng, const float* __restrict__ bnb,
                              const float* __restrict__ bnm, const float* __restrict__ bnv) {
    int b = blockIdx.x, br = blockIdx.y;
    __shared__ float xs[2][512];
    const float* ms = br ? g_MS2 : g_MS1;
    const float* rl = br ? g_RL2 : g_RL1;
    for (int i = threadIdx.x; i < 512; i += 384) {
        xs[0][i] = ms[b * 512 + i];
        xs[1][i] = rl[b * 512 + i];
    }
    __syncthreads();
    int t = threadIdx.x;
    int ci = t >> 7, o = t & 127;
    int ks = 2 + ci;
    const float* w = (ci == 0) ? cw0 : ((ci == 1) ? cw1 : cw2);
    float wreg[2][4];
    for (int c = 0; c < 2; c++)
        for (int q = 0; q < 4; q++) wreg[c][q] = (q < ks) ? w[(o * 2 + c) * ks + q] : 0.f;
    float bias = cb[ci * 128 + o];
    float inv = rsqrtf(bnv[ci * 128 + o] + 1e-5f);
    float sc = bng[ci * 128 + o] * inv;
    float sh = bnb[ci * 128 + o] + (bias - bnm[ci * 128 + o]) * sc;
    float best = -1e30f;
    int P = 512 - ks + 1;
    for (int p = 0; p < P; p++) {
        float v = 0.f;
        for (int q = 0; q < ks; q++) {
            v += wreg[0][q] * xs[0][p + q];
            v += wreg[1][q] * xs[1][p + q];
        }
        v = fmaxf(v * sc + sh, 0.f);
        best = fmaxf(best, v);
    }
    g_FEAT[b * 768 + br * 384 + ci * 128 + o] = best;
}

// ---- K9: fc + softmax ----
__global__ void fc_kernel(const float* __restrict__ fw, const float* __restrict__ fb,
                          float* __restrict__ out) {
    int b = blockIdx.x;
    int w = threadIdx.x >> 5, lane = threadIdx.x & 31;
    __shared__ float lg[2];
    if (w < 2) {
        float s = 0.f;
        for (int k = lane; k < 768; k += 32) s += fw[w * 768 + k] * g_FEAT[b * 768 + k];
#pragma unroll
        for (int off = 16; off; off >>= 1) s += __shfl_down_sync(0xffffffffu, s, off);
        if (lane == 0) lg[w] = s + fb[w];
    }
    __syncthreads();
    if (threadIdx.x == 0) {
        float m = fmaxf(lg[0], lg[1]);
        float e0 = expf(lg[0] - m), e1 = expf(lg[1] - m);
        float inv = 1.f / (e0 + e1);
        out[b * 2 + 0] = e0 * inv;
        out[b * 2 + 1] = e1 * inv;
    }
}

extern "C" void kernel_launch(void* const* d_in, const int* in_sizes, int n_in,
                              void* d_out, int out_size) {
    const int* word1 = (const int*)d_in[0];
    const int* word2 = (const int*)d_in[1];
    const int* piny1 = (const int*)d_in[2];
    const int* piny2 = (const int*)d_in[3];
    const int* len1  = (const int*)d_in[4];
    const int* len2  = (const int*)d_in[5];
    const int* tb1   = (const int*)d_in[6];
    const int* te1   = (const int*)d_in[7];
    const int* tb2   = (const int*)d_in[8];
    const int* te2   = (const int*)d_in[9];
    const float* ew  = (const float*)d_in[10];
    const float* ep  = (const float*)d_in[11];
    const float* pe  = (const float*)d_in[12];
    const float* wih = (const float*)d_in[13];
    const float* whh = (const float*)d_in[14];
    const float* bih = (const float*)d_in[15];
    const float* bhh = (const float*)d_in[16];
    const float* cw0 = (const float*)d_in[17];
    const float* cw1 = (const float*)d_in[18];
    const float* cw2 = (const float*)d_in[19];
    const float* cb  = (const float*)d_in[20];
    const float* bng = (const float*)d_in[21];
    const float* bnb = (const float*)d_in[22];
    const float* bnm = (const float*)d_in[23];
    const float* bnv = (const float*)d_in[24];
    const float* fw  = (const float*)d_in[25];
    const float* fb  = (const float*)d_in[26];
    float* out = (float*)d_out;

    // smem: Wsh/Wsl 24x520 + Hsh/Hsl 64x520 (bf16) + ghs 64x26 f32 + bhs 24 f32
    const int GRU3_SMEM = (24*520*2 + 64*520*2) * 2 + 64*26*4 + 24*4;
    cudaFuncSetAttribute(gru_persist3, cudaFuncAttributeMaxDynamicSharedMemorySize, GRU3_SMEM);

    wconv<<<9984, 256>>>(wih);
    embed_pack<<<dim3(64, 512), 128>>>(word1, word2, piny1, piny2,
                                       tb1, te1, tb2, te2, ew, ep, pe);
    gemm_gi_mma<<<dim3(24, 256), 256>>>(bih);
    zero_bar<<<1, 1>>>();
    gru_persist3<<<128, 128, GRU3_SMEM>>>(whh, bhh, len1, len2);
    norms_kernel<<<dim3(64, 64), 256>>>();
    sim_gemm<<<dim3(4, 4, 32), 256>>>();
    rowmax_kernel<<<dim3(32, 64), 256>>>();
    colmax_kernel<<<dim3(32, 16), 256>>>();
    branch_kernel<<<dim3(32, 2), 384>>>(cw0, cw1, cw2, cb, bng, bnb, bnm, bnv);
    fc_kernel<<<32, 64>>>(fw, fb, out);
}

// round 14
// speedup vs baseline: 2.1110x; 1.0451x over previous
#include <cuda_runtime.h>
#include <cuda_bf16.h>
#include <cstdint>
#include <math.h>

#define LSEQ 512
#define HDIM 512
#define NSEQ 64
#define NSTREAM 128

// ---- scratch (device globals) ----
__device__ __nv_bfloat16 g_Ah[(size_t)NSEQ * LSEQ * 832];   // input hi
__device__ __nv_bfloat16 g_Al[(size_t)NSEQ * LSEQ * 832];   // input lo
__device__ __nv_bfloat16 g_Bh[(size_t)3072 * 832];          // wih hi
__device__ __nv_bfloat16 g_Bl[(size_t)3072 * 832];          // wih lo
__device__ float g_GI[(size_t)NSEQ * LSEQ * 3072];
__device__ __nv_bfloat16 g_Hh[2][NSTREAM * HDIM];           // hidden hi (ping-pong)
__device__ __nv_bfloat16 g_Hl[2][NSTREAM * HDIM];           // hidden lo (ping-pong)
__device__ float g_ENC[(size_t)NSEQ * LSEQ * 1024];
__device__ float g_N[NSEQ * LSEQ];
__device__ float g_SIM[(size_t)32 * LSEQ * LSEQ];
__device__ float g_MS1[32 * LSEQ], g_RL1[32 * LSEQ];
__device__ float g_MS2[32 * LSEQ], g_RL2[32 * LSEQ];
__device__ float g_FEAT[32 * 768];
__device__ unsigned g_bar_ctr[2 * 32];                      // per-dir monotonic, 128B apart

// ---- K1: pack [word | pinyin | pe(l) | pe(tb) | pe(te) | pe(te-l) | pe(l-tb)] as bf16 hi/lo ----
__global__ void embed_pack(const int* __restrict__ w0, const int* __restrict__ w1,
                           const int* __restrict__ py0, const int* __restrict__ py1,
                           const int* __restrict__ tb0, const int* __restrict__ te0,
                           const int* __restrict__ tb1, const int* __restrict__ te1,
                           const float* __restrict__ ew, const float* __restrict__ ep,
                           const float* __restrict__ pe) {
    int seq = blockIdx.x, l = blockIdx.y;
    int side = seq >> 5, b = seq & 31;
    int widx = (side ? w1 : w0)[b * 512 + l];
    int pidx = (side ? py1 : py0)[b * 512 + l];
    int tb = (side ? tb1 : tb0)[b * 512 + l];
    int te = (side ? te1 : te0)[b * 512 + l];
    for (int c = threadIdx.x; c < 832; c += 128) {
        float x;
        if (c < 256) x = ew[(size_t)widx * 256 + c];
        else if (c < 512) x = ep[(size_t)pidx * 256 + (c - 256)];
        else {
            int slot = (c - 512) >> 6, kk = (c - 512) & 63;
            int idx = (slot == 0) ? l : (slot == 1) ? tb : (slot == 2) ? te
                      : (slot == 3) ? (te - l) : (l - tb);
            x = pe[idx * 64 + kk];
        }
        __nv_bfloat16 hi = __float2bfloat16(x);
        __nv_bfloat16 lo = __float2bfloat16(x - __bfloat162float(hi));
        size_t o = (size_t)(seq * 512 + l) * 832 + c;
        g_Ah[o] = hi;
        g_Al[o] = lo;
    }
}

// ---- K1b: split wih into bf16 hi/lo (also resets the GRU barrier counters) ----
__global__ void wconv(const float* __restrict__ wih) {
    if (blockIdx.x == 0 && threadIdx.x == 0) {
        g_bar_ctr[0] = 0u;
        g_bar_ctr[32] = 0u;
    }
    int i = blockIdx.x * 256 + threadIdx.x;
    if (i < 3072 * 832) {
        float x = wih[i];
        __nv_bfloat16 hi = __float2bfloat16(x);
        __nv_bfloat16 lo = __float2bfloat16(x - __bfloat162float(hi));
        g_Bh[i] = hi;
        g_Bl[i] = lo;
    }
}

#define MMA_BF16(d, a, b0v, b1v)                                             \
    asm volatile("mma.sync.aligned.m16n8k16.row.col.f32.bf16.bf16.f32 "      \
                 "{%0,%1,%2,%3}, {%4,%5,%6,%7}, {%8,%9}, {%0,%1,%2,%3};"     \
                 : "+f"(d[0]), "+f"(d[1]), "+f"(d[2]), "+f"(d[3])            \
                 : "r"(a[0]), "r"(a[1]), "r"(a[2]), "r"(a[3]),               \
                   "r"(b0v), "r"(b1v));

// ---- K2: GI = X @ Wih^T + bih  via bf16-split mma.  M=32768 N=3072 K=832 ----
__global__ __launch_bounds__(256) void gemm_gi_mma(const float* __restrict__ bih) {
    __shared__ __align__(16) __nv_bfloat16 Ah[128][40];
    __shared__ __align__(16) __nv_bfloat16 Al[128][40];
    __shared__ __align__(16) __nv_bfloat16 Bh[128][40];
    __shared__ __align__(16) __nv_bfloat16 Bl[128][40];
    int tid = threadIdx.x;
    int n0 = blockIdx.x * 128, m0 = blockIdx.y * 128;
    int wid = tid >> 5, lane = tid & 31;
    int grp = lane >> 2, qp2 = (lane & 3) * 2;
    int wm = (wid >> 2) * 64, wn = (wid & 3) * 32;
    float acc[4][4][4];
#pragma unroll
    for (int i = 0; i < 4; i++)
#pragma unroll
        for (int j = 0; j < 4; j++)
#pragma unroll
            for (int q = 0; q < 4; q++) acc[i][j][q] = 0.f;

    for (int c = 0; c < 26; c++) {
        int k0 = c * 32;
        __syncthreads();
#pragma unroll
        for (int p = 0; p < 2; p++) {
            int t2 = tid + p * 256;
            int row = t2 >> 2, kc = (t2 & 3) * 8;
            *(uint4*)&Ah[row][kc] = *(const uint4*)(g_Ah + (size_t)(m0 + row) * 832 + k0 + kc);
            *(uint4*)&Al[row][kc] = *(const uint4*)(g_Al + (size_t)(m0 + row) * 832 + k0 + kc);
            *(uint4*)&Bh[row][kc] = *(const uint4*)(g_Bh + (size_t)(n0 + row) * 832 + k0 + kc);
            *(uint4*)&Bl[row][kc] = *(const uint4*)(g_Bl + (size_t)(n0 + row) * 832 + k0 + kc);
        }
        __syncthreads();
#pragma unroll
        for (int kk = 0; kk < 32; kk += 16) {
            uint32_t ah[4][4], al[4][4];
#pragma unroll
            for (int i = 0; i < 4; i++) {
                int r = wm + i * 16 + grp;
                ah[i][0] = *(uint32_t*)&Ah[r][kk + qp2];
                ah[i][1] = *(uint32_t*)&Ah[r + 8][kk + qp2];
                ah[i][2] = *(uint32_t*)&Ah[r][kk + 8 + qp2];
                ah[i][3] = *(uint32_t*)&Ah[r + 8][kk + 8 + qp2];
                al[i][0] = *(uint32_t*)&Al[r][kk + qp2];
                al[i][1] = *(uint32_t*)&Al[r + 8][kk + qp2];
                al[i][2] = *(uint32_t*)&Al[r][kk + 8 + qp2];
                al[i][3] = *(uint32_t*)&Al[r + 8][kk + 8 + qp2];
            }
#pragma unroll
            for (int j = 0; j < 4; j++) {
                int nr = wn + j * 8 + grp;
                uint32_t bh0 = *(uint32_t*)&Bh[nr][kk + qp2];
                uint32_t bh1 = *(uint32_t*)&Bh[nr][kk + 8 + qp2];
                uint32_t bl0 = *(uint32_t*)&Bl[nr][kk + qp2];
                uint32_t bl1 = *(uint32_t*)&Bl[nr][kk + 8 + qp2];
#pragma unroll
                for (int i = 0; i < 4; i++) {
                    MMA_BF16(acc[i][j], ah[i], bh0, bh1);
                    MMA_BF16(acc[i][j], ah[i], bl0, bl1);
                    MMA_BF16(acc[i][j], al[i], bh0, bh1);
                }
            }
        }
    }
#pragma unroll
    for (int i = 0; i < 4; i++) {
        int r0 = m0 + wm + i * 16 + grp;
#pragma unroll
        for (int j = 0; j < 4; j++) {
            int cidx = n0 + wn + j * 8 + qp2;
            float2 bb = *(const float2*)&bih[cidx];
            float2 v0 = make_float2(acc[i][j][0] + bb.x, acc[i][j][1] + bb.y);
            float2 v1 = make_float2(acc[i][j][2] + bb.x, acc[i][j][3] + bb.y);
            *(float2*)&g_GI[(size_t)r0 * 3072 + cidx] = v0;
            *(float2*)&g_GI[(size_t)(r0 + 8) * 3072 + cidx] = v1;
        }
    }
}

// ---- MMA K-range body for the recurrence ----
__device__ __forceinline__ void mma_khalf(
    const __nv_bfloat16* __restrict__ Hsh, const __nv_bfloat16* __restrict__ Hsl,
    const __nv_bfloat16* __restrict__ Wsh, const __nv_bfloat16* __restrict__ Wsl,
    int r, int grp, int qp2, int k0, int k1, float acc[3][4]) {
    const __nv_bfloat16* Ha = Hsh + r * 520;
    const __nv_bfloat16* Hb = Hsh + (r + 8) * 520;
    const __nv_bfloat16* La = Hsl + r * 520;
    const __nv_bfloat16* Lb = Hsl + (r + 8) * 520;
#pragma unroll 4
    for (int kk = k0; kk < k1; kk += 16) {
        uint32_t ah[4], al[4];
        ah[0] = *(const uint32_t*)(Ha + kk + qp2);
        ah[1] = *(const uint32_t*)(Hb + kk + qp2);
        ah[2] = *(const uint32_t*)(Ha + kk + 8 + qp2);
        ah[3] = *(const uint32_t*)(Hb + kk + 8 + qp2);
        al[0] = *(const uint32_t*)(La + kk + qp2);
        al[1] = *(const uint32_t*)(Lb + kk + qp2);
        al[2] = *(const uint32_t*)(La + kk + 8 + qp2);
        al[3] = *(const uint32_t*)(Lb + kk + 8 + qp2);
#pragma unroll
        for (int nt = 0; nt < 3; nt++) {
            const __nv_bfloat16* Wr = Wsh + (nt * 8 + grp) * 520 + kk;
            const __nv_bfloat16* Wx = Wsl + (nt * 8 + grp) * 520 + kk;
            uint32_t bh0 = *(const uint32_t*)(Wr + qp2);
            uint32_t bh1 = *(const uint32_t*)(Wr + 8 + qp2);
            uint32_t bl0 = *(const uint32_t*)(Wx + qp2);
            uint32_t bl1 = *(const uint32_t*)(Wx + 8 + qp2);
            MMA_BF16(acc[nt], ah, bh0, bh1);
            MMA_BF16(acc[nt], ah, bl0, bl1);
            MMA_BF16(acc[nt], al, bh0, bh1);
        }
    }
}

// ---- K3: persistent bidirectional GRU; 8 warps = (m-tile x K-half) split ----
// 128 blocks x 256 thr. Block = (dir d, hidden-col tile j0..j0+7).
__global__ __launch_bounds__(256) void gru_persist4(
    const float* __restrict__ Whh, const float* __restrict__ bhh,
    const int* __restrict__ len1, const int* __restrict__ len2) {
    extern __shared__ __align__(16) unsigned char smem_raw[];
    __nv_bfloat16* Wsh = (__nv_bfloat16*)smem_raw;          // [24][520]
    __nv_bfloat16* Wsl = Wsh + 24 * 520;
    __nv_bfloat16* Hsh = Wsl + 24 * 520;                    // [64][520]
    __nv_bfloat16* Hsl = Hsh + 64 * 520;
    float* ghs = (float*)(Hsl + 64 * 520);                  // [2][64][26]
    float* bhs = ghs + 2 * 64 * 26;                         // [24]

    int bx = blockIdx.x, tid = threadIdx.x;
    int d = bx >> 6, jt = bx & 63, j0 = jt * 8;
    int wid = tid >> 5, lane = tid & 31;
    int grp = lane >> 2, qp2 = (lane & 3) * 2;
    int kh = wid & 1, mt = wid >> 1;          // K-half, m-tile
    int r = mt * 16 + grp;
    int kbase = kh * 256;

    // one-time Whh tile (24 rows: gate g of col j0+jl), bf16 hi/lo
    for (int i = tid; i < 24 * 512; i += 256) {
        int n = i >> 9, k = i & 511;
        int row = (n >> 3) * 512 + j0 + (n & 7);
        float x = Whh[((size_t)d * 1536 + row) * 512 + k];
        __nv_bfloat16 hi = __float2bfloat16(x);
        Wsh[n * 520 + k] = hi;
        Wsl[n * 520 + k] = __float2bfloat16(x - __bfloat162float(hi));
    }
    if (tid < 24) bhs[tid] = bhh[d * 1536 + (tid >> 3) * 512 + j0 + (tid & 7)];

    // per-thread state: 2 (sl, jl) pairs; lens preloaded
    int sl_r[2], jl_r[2], len_r[2];
    float hloc[2];
#pragma unroll
    for (int q = 0; q < 2; q++) {
        int i = tid + q * 256;
        sl_r[q] = i >> 3; jl_r[q] = i & 7;
        int side = sl_r[q] >> 5, b = sl_r[q] & 31;
        len_r[q] = side ? len2[b] : len1[b];
        hloc[q] = 0.f;
        g_Hh[0][(d * 64 + sl_r[q]) * 512 + j0 + jl_r[q]] = __float2bfloat16(0.f);
        g_Hl[0][(d * 64 + sl_r[q]) * 512 + j0 + jl_r[q]] = __float2bfloat16(0.f);
    }
    __syncthreads();
    if (tid == 0) { __threadfence(); atomicAdd(&g_bar_ctr[d * 32], 1u); }

    for (int t = 0; t < LSEQ; t++) {
        // ---- prefetch gi(t) into registers (independent of barrier) ----
        float gpre[2][3]; int lp_r[2]; bool valid_r[2];
#pragma unroll
        for (int q = 0; q < 2; q++) {
            bool valid = (t < len_r[q]);
            int lp = (d == 1 && valid) ? (len_r[q] - 1 - t) : t;
            const float* gi = g_GI + ((size_t)(sl_r[q] * 512 + lp)) * 3072 + d * 1536 + j0 + jl_r[q];
            gpre[q][0] = gi[0]; gpre[q][1] = gi[512]; gpre[q][2] = gi[1024];
            lp_r[q] = lp; valid_r[q] = valid;
        }

        // ---- wait for H(t) published by all 64 blocks of this dir ----
        if (tid == 0) {
            unsigned tgt = 64u * (unsigned)(t + 1);
            volatile unsigned* p = &g_bar_ctr[d * 32];
            int bo = 8;
            while (*p < tgt) { __nanosleep(bo); if (bo < 128) bo += bo; }
            __threadfence();
        }
        __syncthreads();

        // ---- cp.async full H (ping buffer t&1) ----
        const char* baseH = (const char*)(g_Hh[t & 1] + (size_t)d * 64 * 512);
        const char* baseL = (const char*)(g_Hl[t & 1] + (size_t)d * 64 * 512);
        for (int i = tid; i < 64 * 64; i += 256) {
            int rr = i >> 6, kq = i & 63;
            unsigned dH = (unsigned)__cvta_generic_to_shared(Hsh + rr * 520) + kq * 16;
            unsigned dL = (unsigned)__cvta_generic_to_shared(Hsl + rr * 520) + kq * 16;
            const char* sH = baseH + (rr * 64 + kq) * 16;
            const char* sL = baseL + (rr * 64 + kq) * 16;
            asm volatile("cp.async.cg.shared.global [%0], [%1], 16;" :: "r"(dH), "l"(sH));
            asm volatile("cp.async.cg.shared.global [%0], [%1], 16;" :: "r"(dL), "l"(sL));
        }
        asm volatile("cp.async.commit_group;");
        float acc[3][4];
#pragma unroll
        for (int nt = 0; nt < 3; nt++)
#pragma unroll
            for (int q = 0; q < 4; q++) acc[nt][q] = 0.f;
        asm volatile("cp.async.wait_group 0;" ::: "memory");
        __syncthreads();

        // ---- warp's K-slice MMA (2 warps per SMSP now) ----
        mma_khalf(Hsh, Hsl, Wsh, Wsl, r, grp, qp2, kbase, kbase + 256, acc);

        // stage partial gh to smem [kh]
        float* gh_o = ghs + kh * (64 * 26);
#pragma unroll
        for (int nt = 0; nt < 3; nt++) {
            gh_o[r * 26 + nt * 8 + qp2]           = acc[nt][0];
            gh_o[r * 26 + nt * 8 + qp2 + 1]       = acc[nt][1];
            gh_o[(r + 8) * 26 + nt * 8 + qp2]     = acc[nt][2];
            gh_o[(r + 8) * 26 + nt * 8 + qp2 + 1] = acc[nt][3];
        }
        __syncthreads();

        // ---- gates + state update; publish H(t+1) to pong buffer, arrive early ----
        float enc_r[2];
        __nv_bfloat16* outH = g_Hh[(t + 1) & 1] + (size_t)d * 64 * 512;
        __nv_bfloat16* outL = g_Hl[(t + 1) & 1] + (size_t)d * 64 * 512;
#pragma unroll
        for (int q = 0; q < 2; q++) {
            int sl = sl_r[q], jl = jl_r[q];
            float ghr = ghs[sl * 26 + jl]      + ghs[1664 + sl * 26 + jl]      + bhs[jl];
            float ghz = ghs[sl * 26 + 8 + jl]  + ghs[1664 + sl * 26 + 8 + jl]  + bhs[8 + jl];
            float ghn = ghs[sl * 26 + 16 + jl] + ghs[1664 + sl * 26 + 16 + jl] + bhs[16 + jl];
            float h = hloc[q];
            float rg = 1.f / (1.f + __expf(-(gpre[q][0] + ghr)));
            float zg = 1.f / (1.f + __expf(-(gpre[q][1] + ghz)));
            float ng = tanhf(gpre[q][2] + rg * ghn);
            float hnew = (1.f - zg) * ng + zg * h;
            float hout = valid_r[q] ? hnew : h;
            hloc[q] = hout;
            __nv_bfloat16 hi = __float2bfloat16(hout);
            outH[sl * 512 + j0 + jl] = hi;
            outL[sl * 512 + j0 + jl] = __float2bfloat16(hout - __bfloat162float(hi));
            enc_r[q] = valid_r[q] ? hnew : 0.f;
        }
        __syncthreads();
        if (tid == 0) { __threadfence(); atomicAdd(&g_bar_ctr[d * 32], 1u); }
        // ENC stores off the critical path
#pragma unroll
        for (int q = 0; q < 2; q++)
            g_ENC[((size_t)(sl_r[q] * 512 + lp_r[q])) * 1024 + d * 512 + j0 + jl_r[q]] = enc_r[q];
    }
}

// ---- K4: row norms ----
__global__ void norms_kernel() {
    int seq = blockIdx.x;
    int w = threadIdx.x >> 5, lane = threadIdx.x & 31;
    int i = blockIdx.y * 8 + w;
    const float* row = g_ENC + ((size_t)seq * 512 + i) * 1024;
    float sacc = 0.f;
    for (int k = lane; k < 1024; k += 32) { float v = row[k]; sacc += v * v; }
#pragma unroll
    for (int off = 16; off; off >>= 1) sacc += __shfl_down_sync(0xffffffffu, sacc, off);
    if (lane == 0) g_N[seq * 512 + i] = sqrtf(sacc);
}

// ---- K5: SIM[b] = enc1[b] @ enc2[b]^T / max(n1*n2, eps) ----
__global__ __launch_bounds__(256) void sim_gemm() {
    int b = blockIdx.z;
    int n0 = blockIdx.x * 128, m0 = blockIdx.y * 128;
    __shared__ float As[16][132];
    __shared__ float Bs[16][132];
    const float* A = g_ENC + ((size_t)b * 512 + m0) * 1024;
    const float* Bp = g_ENC + ((size_t)(32 + b) * 512 + n0) * 1024;
    int tid = threadIdx.x;
    int tx = tid % 16, ty = tid / 16;
    int lr = tid >> 2, lc = (tid & 3) << 2;
    float acc[8][8];
#pragma unroll
    for (int i = 0; i < 8; i++)
#pragma unroll
        for (int j = 0; j < 8; j++) acc[i][j] = 0.f;
    for (int kc = 0; kc < 64; kc++) {
        int K0 = kc * 16;
        float4 ra0 = *(const float4*)(A + (size_t)lr * 1024 + K0 + lc);
        float4 ra1 = *(const float4*)(A + (size_t)(lr + 64) * 1024 + K0 + lc);
        float4 rb0 = *(const float4*)(Bp + (size_t)lr * 1024 + K0 + lc);
        float4 rb1 = *(const float4*)(Bp + (size_t)(lr + 64) * 1024 + K0 + lc);
        __syncthreads();
        As[lc+0][lr]=ra0.x; As[lc+1][lr]=ra0.y; As[lc+2][lr]=ra0.z; As[lc+3][lr]=ra0.w;
        As[lc+0][lr+64]=ra1.x; As[lc+1][lr+64]=ra1.y; As[lc+2][lr+64]=ra1.z; As[lc+3][lr+64]=ra1.w;
        Bs[lc+0][lr]=rb0.x; Bs[lc+1][lr]=rb0.y; Bs[lc+2][lr]=rb0.z; Bs[lc+3][lr]=rb0.w;
        Bs[lc+0][lr+64]=rb1.x; Bs[lc+1][lr+64]=rb1.y; Bs[lc+2][lr+64]=rb1.z; Bs[lc+3][lr+64]=rb1.w;
        __syncthreads();
#pragma unroll
        for (int kk = 0; kk < 16; kk++) {
            float4 a0 = *(const float4*)&As[kk][ty * 8];
            float4 a1 = *(const float4*)&As[kk][ty * 8 + 4];
            float4 b0 = *(const float4*)&Bs[kk][tx * 8];
            float4 b1 = *(const float4*)&Bs[kk][tx * 8 + 4];
            float av[8] = {a0.x,a0.y,a0.z,a0.w,a1.x,a1.y,a1.z,a1.w};
            float bv[8] = {b0.x,b0.y,b0.z,b0.w,b1.x,b1.y,b1.z,b1.w};
#pragma unroll
            for (int i = 0; i < 8; i++)
#pragma unroll
                for (int j = 0; j < 8; j++) acc[i][j] += av[i] * bv[j];
        }
    }
#pragma unroll
    for (int i = 0; i < 8; i++) {
        int row = m0 + ty * 8 + i;
        float n1 = g_N[b * 512 + row];
        float* dst = g_SIM + ((size_t)b * 512 + row) * 512 + n0 + tx * 8;
#pragma unroll
        for (int j = 0; j < 8; j++) {
            float n2 = g_N[(32 + b) * 512 + n0 + tx * 8 + j];
            dst[j] = acc[i][j] / fmaxf(n1 * n2, 1e-8f);
        }
    }
}

// ---- K6: max/argmax over axis 2 ----
__global__ void rowmax_kernel() {
    int b = blockIdx.x;
    int w = threadIdx.x >> 5, lane = threadIdx.x & 31;
    int i = blockIdx.y * 8 + w;
    const float* row = g_SIM + ((size_t)b * 512 + i) * 512;
    float best = -1e30f; int bi = 0;
    for (int j = lane; j < 512; j += 32) {
        float v = row[j];
        if (v > best) { best = v; bi = j; }
    }
#pragma unroll
    for (int off = 16; off; off >>= 1) {
        float v = __shfl_down_sync(0xffffffffu, best, off);
        int ii = __shfl_down_sync(0xffffffffu, bi, off);
        if (v > best || (v == best && ii < bi)) { best = v; bi = ii; }
    }
    if (lane == 0) {
        g_MS1[b * 512 + i] = best;
        g_RL1[b * 512 + i] = (float)(i - bi);
    }
}

// ---- K7: max/argmax over axis 1 ----
__global__ void colmax_kernel() {
    int b = blockIdx.x, j0 = blockIdx.y * 32;
    int g = threadIdx.x >> 5, j = threadIdx.x & 31;
    float best = -1e30f; int bi = 0;
    const float* S = g_SIM + (size_t)b * 512 * 512;
    for (int i = g; i < 512; i += 8) {
        float v = S[(size_t)i * 512 + j0 + j];
        if (v > best) { best = v; bi = i; }
    }
    __shared__ float sm[256];
    __shared__ int si[256];
    sm[threadIdx.x] = best; si[threadIdx.x] = bi;
    __syncthreads();
    if (g == 0) {
        for (int gg = 1; gg < 8; gg++) {
            float v = sm[gg * 32 + j]; int ii = si[gg * 32 + j];
            if (v > best || (v == best && ii < bi)) { best = v; bi = ii; }
        }
        int jj = j0 + j;
        g_MS2[b * 512 + jj] = best;
        g_RL2[b * 512 + jj] = (float)(jj - bi);
    }
}

// ---- K8: conv branches + BN + ReLU + maxpool ----
__global__ void branch_kernel(const float* __restrict__ cw0, const float* __restrict__ cw1,
                              const float* __restrict__ cw2, const float* __restrict__ cb,
                              const float* __restrict__ bng, const float* __restrict__ bnb,
                              const float* __restrict__ bnm, const float* __restrict__ bnv) {
    int b = blockIdx.x, br = blockIdx.y;
    __shared__ float xs[2][512];
    const float* ms = br ? g_MS2 : g_MS1;
    const float* rl = br ? g_RL2 : g_RL1;
    for (int i = threadIdx.x; i < 512; i += 384) {
        xs[0][i] = ms[b * 512 + i];
        xs[1][i] = rl[b * 512 + i];
    }
    __syncthreads();
    int t = threadIdx.x;
    int ci = t >> 7, o = t & 127;
    int ks = 2 + ci;
    const float* w = (ci == 0) ? cw0 : ((ci == 1) ? cw1 : cw2);
    float wreg[2][4];
    for (int c = 0; c < 2; c++)
        for (int q = 0; q < 4; q++) wreg[c][q] = (q < ks) ? w[(o * 2 + c) * ks + q] : 0.f;
    float bias = cb[ci * 128 + o];
    float inv = rsqrtf(bnv[ci * 128 + o] + 1e-5f);
    float sc = bng[ci * 128 + o] * inv;
    float sh = bnb[ci * 128 + o] + (bias - bnm[ci * 128 + o]) * sc;
    float best = -1e30f;
    int P = 512 - ks + 1;
    for (int p = 0; p < P; p++) {
        float v = 0.f;
        for (int q = 0; q < ks; q++) {
            v += wreg[0][q] * xs[0][p + q];
            v += wreg[1][q] * xs[1][p + q];
        }
        v = fmaxf(v * sc + sh, 0.f);
        best = fmaxf(best, v);
    }
    g_FEAT[b * 768 + br * 384 + ci * 128 + o] = best;
}

// ---- K9: fc + softmax ----
__global__ void fc_kernel(const float* __restrict__ fw, const float* __restrict__ fb,
                          float* __restrict__ out) {
    int b = blockIdx.x;
    int w = threadIdx.x >> 5, lane = threadIdx.x & 31;
    __shared__ float lg[2];
    if (w < 2) {
        float s = 0.f;
        for (int k = lane; k < 768; k += 32) s += fw[w * 768 + k] * g_FEAT[b * 768 + k];
#pragma unroll
        for (int off = 16; off; off >>= 1) s += __shfl_down_sync(0xffffffffu, s, off);
        if (lane == 0) lg[w] = s + fb[w];
    }
    __syncthreads();
    if (threadIdx.x == 0) {
        float m = fmaxf(lg[0], lg[1]);
        float e0 = expf(lg[0] - m), e1 = expf(lg[1] - m);
        float inv = 1.f / (e0 + e1);
        out[b * 2 + 0] = e0 * inv;
        out[b * 2 + 1] = e1 * inv;
    }
}

extern "C" void kernel_launch(void* const* d_in, const int* in_sizes, int n_in,
                              void* d_out, int out_size) {
    const int* word1 = (const int*)d_in[0];
    const int* word2 = (const int*)d_in[1];
    const int* piny1 = (const int*)d_in[2];
    const int* piny2 = (const int*)d_in[3];
    const int* len1  = (const int*)d_in[4];
    const int* len2  = (const int*)d_in[5];
    const int* tb1   = (const int*)d_in[6];
    const int* te1   = (const int*)d_in[7];
    const int* tb2   = (const int*)d_in[8];
    const int* te2   = (const int*)d_in[9];
    const float* ew  = (const float*)d_in[10];
    const float* ep  = (const float*)d_in[11];
    const float* pe  = (const float*)d_in[12];
    const float* wih = (const float*)d_in[13];
    const float* whh = (const float*)d_in[14];
    const float* bih = (const float*)d_in[15];
    const float* bhh = (const float*)d_in[16];
    const float* cw0 = (const float*)d_in[17];
    const float* cw1 = (const float*)d_in[18];
    const float* cw2 = (const float*)d_in[19];
    const float* cb  = (const float*)d_in[20];
    const float* bng = (const float*)d_in[21];
    const float* bnb = (const float*)d_in[22];
    const float* bnm = (const float*)d_in[23];
    const float* bnv = (const float*)d_in[24];
    const float* fw  = (const float*)d_in[25];
    const float* fb  = (const float*)d_in[26];
    float* out = (float*)d_out;

    // smem: Wsh/Wsl 24x520 + Hsh/Hsl 64x520 (bf16) + ghs 2x64x26 f32 + bhs 24 f32
    const int GRU4_SMEM = (24*520*2 + 64*520*2) * 2 + 2*64*26*4 + 24*4;
    cudaFuncSetAttribute(gru_persist4, cudaFuncAttributeMaxDynamicSharedMemorySize, GRU4_SMEM);

    wconv<<<9984, 256>>>(wih);
    embed_pack<<<dim3(64, 512), 128>>>(word1, word2, piny1, piny2,
                                       tb1, te1, tb2, te2, ew, ep, pe);
    gemm_gi_mma<<<dim3(24, 256), 256>>>(bih);
    gru_persist4<<<128, 256, GRU4_SMEM>>>(whh, bhh, len1, len2);
    norms_kernel<<<dim3(64, 64), 256>>>();
    sim_gemm<<<dim3(4, 4, 32), 256>>>();
    rowmax_kernel<<<dim3(32, 64), 256>>>();
    colmax_kernel<<<dim3(32, 16), 256>>>();
    branch_kernel<<<dim3(32, 2), 384>>>(cw0, cw1, cw2, cb, bng, bnb, bnm, bnv);
    fc_kernel<<<32, 64>>>(fw, fb, out);
}

// round 16
// speedup vs baseline: 2.2512x; 1.0664x over previous
#include <cuda_runtime.h>
#include <cuda_bf16.h>
#include <cstdint>
#include <math.h>

#define LSEQ 512
#define HDIM 512
#define NSEQ 64
#define NSTREAM 128

// ---- scratch (device globals) ----
__device__ __nv_bfloat16 g_Ah[(size_t)NSEQ * LSEQ * 832];   // input hi
__device__ __nv_bfloat16 g_Al[(size_t)NSEQ * LSEQ * 832];   // input lo
__device__ __nv_bfloat16 g_Bh[(size_t)3072 * 832];          // wih hi
__device__ __nv_bfloat16 g_Bl[(size_t)3072 * 832];          // wih lo
__device__ float g_GI[(size_t)NSEQ * LSEQ * 3072];
__device__ __nv_bfloat16 g_Hh[2][NSTREAM * HDIM];           // hidden hi (ping-pong)
__device__ __nv_bfloat16 g_Hl[2][NSTREAM * HDIM];           // hidden lo (ping-pong)
__device__ float g_ENC[(size_t)NSEQ * LSEQ * 1024];
__device__ float g_N[NSEQ * LSEQ];
__device__ float g_SIM[(size_t)32 * LSEQ * LSEQ];
__device__ float g_MS1[32 * LSEQ], g_RL1[32 * LSEQ];
__device__ float g_MS2[32 * LSEQ], g_RL2[32 * LSEQ];
__device__ float g_FEAT[32 * 768];
__device__ unsigned g_bar_ctr[2 * 32];                      // per-dir monotonic, 128B apart

__device__ __forceinline__ uint32_t pack_bf2(float a, float b) {
    __nv_bfloat162 p;
    p.x = __float2bfloat16(a);
    p.y = __float2bfloat16(b);
    return *(uint32_t*)&p;
}

// ---- K1: pack [word | pinyin | pe(l) | pe(tb) | pe(te) | pe(te-l) | pe(l-tb)] as bf16 hi/lo ----
__global__ void embed_pack(const int* __restrict__ w0, const int* __restrict__ w1,
                           const int* __restrict__ py0, const int* __restrict__ py1,
                           const int* __restrict__ tb0, const int* __restrict__ te0,
                           const int* __restrict__ tb1, const int* __restrict__ te1,
                           const float* __restrict__ ew, const float* __restrict__ ep,
                           const float* __restrict__ pe) {
    int seq = blockIdx.x, l = blockIdx.y;
    int side = seq >> 5, b = seq & 31;
    int widx = (side ? w1 : w0)[b * 512 + l];
    int pidx = (side ? py1 : py0)[b * 512 + l];
    int tb = (side ? tb1 : tb0)[b * 512 + l];
    int te = (side ? te1 : te0)[b * 512 + l];
    for (int c = threadIdx.x; c < 832; c += 128) {
        float x;
        if (c < 256) x = ew[(size_t)widx * 256 + c];
        else if (c < 512) x = ep[(size_t)pidx * 256 + (c - 256)];
        else {
            int slot = (c - 512) >> 6, kk = (c - 512) & 63;
            int idx = (slot == 0) ? l : (slot == 1) ? tb : (slot == 2) ? te
                      : (slot == 3) ? (te - l) : (l - tb);
            x = pe[idx * 64 + kk];
        }
        __nv_bfloat16 hi = __float2bfloat16(x);
        __nv_bfloat16 lo = __float2bfloat16(x - __bfloat162float(hi));
        size_t o = (size_t)(seq * 512 + l) * 832 + c;
        g_Ah[o] = hi;
        g_Al[o] = lo;
    }
}

// ---- K1b: split wih into bf16 hi/lo (also resets the GRU barrier counters) ----
__global__ void wconv(const float* __restrict__ wih) {
    if (blockIdx.x == 0 && threadIdx.x == 0) {
        g_bar_ctr[0] = 0u;
        g_bar_ctr[32] = 0u;
    }
    int i = blockIdx.x * 256 + threadIdx.x;
    if (i < 3072 * 832) {
        float x = wih[i];
        __nv_bfloat16 hi = __float2bfloat16(x);
        __nv_bfloat16 lo = __float2bfloat16(x - __bfloat162float(hi));
        g_Bh[i] = hi;
        g_Bl[i] = lo;
    }
}

#define MMA_BF16(d, a, b0v, b1v)                                             \
    asm volatile("mma.sync.aligned.m16n8k16.row.col.f32.bf16.bf16.f32 "      \
                 "{%0,%1,%2,%3}, {%4,%5,%6,%7}, {%8,%9}, {%0,%1,%2,%3};"     \
                 : "+f"(d[0]), "+f"(d[1]), "+f"(d[2]), "+f"(d[3])            \
                 : "r"(a[0]), "r"(a[1]), "r"(a[2]), "r"(a[3]),               \
                   "r"(b0v), "r"(b1v));

// ---- K2: GI = X @ Wih^T + bih  via bf16-split mma.  M=32768 N=3072 K=832 ----
__global__ __launch_bounds__(256) void gemm_gi_mma(const float* __restrict__ bih) {
    __shared__ __align__(16) __nv_bfloat16 Ah[128][40];
    __shared__ __align__(16) __nv_bfloat16 Al[128][40];
    __shared__ __align__(16) __nv_bfloat16 Bh[128][40];
    __shared__ __align__(16) __nv_bfloat16 Bl[128][40];
    int tid = threadIdx.x;
    int n0 = blockIdx.x * 128, m0 = blockIdx.y * 128;
    int wid = tid >> 5, lane = tid & 31;
    int grp = lane >> 2, qp2 = (lane & 3) * 2;
    int wm = (wid >> 2) * 64, wn = (wid & 3) * 32;
    float acc[4][4][4];
#pragma unroll
    for (int i = 0; i < 4; i++)
#pragma unroll
        for (int j = 0; j < 4; j++)
#pragma unroll
            for (int q = 0; q < 4; q++) acc[i][j][q] = 0.f;

    for (int c = 0; c < 26; c++) {
        int k0 = c * 32;
        __syncthreads();
#pragma unroll
        for (int p = 0; p < 2; p++) {
            int t2 = tid + p * 256;
            int row = t2 >> 2, kc = (t2 & 3) * 8;
            *(uint4*)&Ah[row][kc] = *(const uint4*)(g_Ah + (size_t)(m0 + row) * 832 + k0 + kc);
            *(uint4*)&Al[row][kc] = *(const uint4*)(g_Al + (size_t)(m0 + row) * 832 + k0 + kc);
            *(uint4*)&Bh[row][kc] = *(const uint4*)(g_Bh + (size_t)(n0 + row) * 832 + k0 + kc);
            *(uint4*)&Bl[row][kc] = *(const uint4*)(g_Bl + (size_t)(n0 + row) * 832 + k0 + kc);
        }
        __syncthreads();
#pragma unroll
        for (int kk = 0; kk < 32; kk += 16) {
            uint32_t ah[4][4], al[4][4];
#pragma unroll
            for (int i = 0; i < 4; i++) {
                int r = wm + i * 16 + grp;
                ah[i][0] = *(uint32_t*)&Ah[r][kk + qp2];
                ah[i][1] = *(uint32_t*)&Ah[r + 8][kk + qp2];
                ah[i][2] = *(uint32_t*)&Ah[r][kk + 8 + qp2];
                ah[i][3] = *(uint32_t*)&Ah[r + 8][kk + 8 + qp2];
                al[i][0] = *(uint32_t*)&Al[r][kk + qp2];
                al[i][1] = *(uint32_t*)&Al[r + 8][kk + qp2];
                al[i][2] = *(uint32_t*)&Al[r][kk + 8 + qp2];
                al[i][3] = *(uint32_t*)&Al[r + 8][kk + 8 + qp2];
            }
#pragma unroll
            for (int j = 0; j < 4; j++) {
                int nr = wn + j * 8 + grp;
                uint32_t bh0 = *(uint32_t*)&Bh[nr][kk + qp2];
                uint32_t bh1 = *(uint32_t*)&Bh[nr][kk + 8 + qp2];
                uint32_t bl0 = *(uint32_t*)&Bl[nr][kk + qp2];
                uint32_t bl1 = *(uint32_t*)&Bl[nr][kk + 8 + qp2];
#pragma unroll
                for (int i = 0; i < 4; i++) {
                    MMA_BF16(acc[i][j], ah[i], bh0, bh1);
                    MMA_BF16(acc[i][j], ah[i], bl0, bl1);
                    MMA_BF16(acc[i][j], al[i], bh0, bh1);
                }
            }
        }
    }
#pragma unroll
    for (int i = 0; i < 4; i++) {
        int r0 = m0 + wm + i * 16 + grp;
#pragma unroll
        for (int j = 0; j < 4; j++) {
            int cidx = n0 + wn + j * 8 + qp2;
            float2 bb = *(const float2*)&bih[cidx];
            float2 v0 = make_float2(acc[i][j][0] + bb.x, acc[i][j][1] + bb.y);
            float2 v1 = make_float2(acc[i][j][2] + bb.x, acc[i][j][3] + bb.y);
            *(float2*)&g_GI[(size_t)r0 * 3072 + cidx] = v0;
            *(float2*)&g_GI[(size_t)(r0 + 8) * 3072 + cidx] = v1;
        }
    }
}

// ---- MMA K-range body for the recurrence ----
__device__ __forceinline__ void mma_khalf(
    const __nv_bfloat16* __restrict__ Hsh, const __nv_bfloat16* __restrict__ Hsl,
    const __nv_bfloat16* __restrict__ Wsh, const __nv_bfloat16* __restrict__ Wsl,
    int r, int grp, int qp2, int k0, int k1, float acc[3][4]) {
    const __nv_bfloat16* Ha = Hsh + r * 520;
    const __nv_bfloat16* Hb = Hsh + (r + 8) * 520;
    const __nv_bfloat16* La = Hsl + r * 520;
    const __nv_bfloat16* Lb = Hsl + (r + 8) * 520;
#pragma unroll 4
    for (int kk = k0; kk < k1; kk += 16) {
        uint32_t ah[4], al[4];
        ah[0] = *(const uint32_t*)(Ha + kk + qp2);
        ah[1] = *(const uint32_t*)(Hb + kk + qp2);
        ah[2] = *(const uint32_t*)(Ha + kk + 8 + qp2);
        ah[3] = *(const uint32_t*)(Hb + kk + 8 + qp2);
        al[0] = *(const uint32_t*)(La + kk + qp2);
        al[1] = *(const uint32_t*)(Lb + kk + qp2);
        al[2] = *(const uint32_t*)(La + kk + 8 + qp2);
        al[3] = *(const uint32_t*)(Lb + kk + 8 + qp2);
#pragma unroll
        for (int nt = 0; nt < 3; nt++) {
            const __nv_bfloat16* Wr = Wsh + (nt * 8 + grp) * 520 + kk;
            const __nv_bfloat16* Wx = Wsl + (nt * 8 + grp) * 520 + kk;
            uint32_t bh0 = *(const uint32_t*)(Wr + qp2);
            uint32_t bh1 = *(const uint32_t*)(Wr + 8 + qp2);
            uint32_t bl0 = *(const uint32_t*)(Wx + qp2);
            uint32_t bl1 = *(const uint32_t*)(Wx + 8 + qp2);
            MMA_BF16(acc[nt], ah, bh0, bh1);
            MMA_BF16(acc[nt], ah, bl0, bl1);
            MMA_BF16(acc[nt], al, bh0, bh1);
        }
    }
}

// ---- K3: persistent bidirectional GRU; warp-private H fill, per-warp poll ----
// 128 blocks x 256 thr. Block = (dir d, hidden-col tile j0..j0+7).
__global__ __launch_bounds__(256) void gru_persist5(
    const float* __restrict__ Whh, const float* __restrict__ bhh,
    const int* __restrict__ len1, const int* __restrict__ len2) {
    extern __shared__ __align__(16) unsigned char smem_raw[];
    __nv_bfloat16* Wsh = (__nv_bfloat16*)smem_raw;          // [24][520]
    __nv_bfloat16* Wsl = Wsh + 24 * 520;
    __nv_bfloat16* Hsh = Wsl + 24 * 520;                    // [64][520]
    __nv_bfloat16* Hsl = Hsh + 64 * 520;
    float* ghs = (float*)(Hsl + 64 * 520);                  // [2][64][26]
    float* bhs = ghs + 2 * 64 * 26;                         // [24]

    int bx = blockIdx.x, tid = threadIdx.x;
    int d = bx >> 6, jt = bx & 63, j0 = jt * 8;
    int wid = tid >> 5, lane = tid & 31;
    int grp = lane >> 2, qp2 = (lane & 3) * 2;
    int kh = wid & 1, mt = wid >> 1;          // K-half, m-tile
    int r = mt * 16 + grp;
    int kbase = kh * 256;
    int R0 = mt * 16;

    // one-time Whh tile (24 rows: gate g of col j0+jl), bf16 hi/lo
    for (int i = tid; i < 24 * 512; i += 256) {
        int n = i >> 9, k = i & 511;
        int row = (n >> 3) * 512 + j0 + (n & 7);
        float x = Whh[((size_t)d * 1536 + row) * 512 + k];
        __nv_bfloat16 hi = __float2bfloat16(x);
        Wsh[n * 520 + k] = hi;
        Wsl[n * 520 + k] = __float2bfloat16(x - __bfloat162float(hi));
    }
    if (tid < 24) bhs[tid] = bhh[d * 1536 + (tid >> 3) * 512 + j0 + (tid & 7)];

    // per-thread state: 2 (sl, jl) pairs; lens preloaded
    int sl_r[2], jl_r[2], len_r[2];
    float hloc[2];
#pragma unroll
    for (int q = 0; q < 2; q++) {
        int i = tid + q * 256;
        sl_r[q] = i >> 3; jl_r[q] = i & 7;
        int side = sl_r[q] >> 5, b = sl_r[q] & 31;
        len_r[q] = side ? len2[b] : len1[b];
        hloc[q] = 0.f;
        g_Hh[0][(d * 64 + sl_r[q]) * 512 + j0 + jl_r[q]] = __float2bfloat16(0.f);
        g_Hl[0][(d * 64 + sl_r[q]) * 512 + j0 + jl_r[q]] = __float2bfloat16(0.f);
    }
    __syncthreads();
    if (tid == 0) { __threadfence(); atomicAdd(&g_bar_ctr[d * 32], 1u); }

    for (int t = 0; t < LSEQ; t++) {
        // ---- prefetch gi(t) into registers (independent of barrier) ----
        float gpre[2][3]; int lp_r[2]; bool valid_r[2];
#pragma unroll
        for (int q = 0; q < 2; q++) {
            bool valid = (t < len_r[q]);
            int lp = (d == 1 && valid) ? (len_r[q] - 1 - t) : t;
            const float* gi = g_GI + ((size_t)(sl_r[q] * 512 + lp)) * 3072 + d * 1536 + j0 + jl_r[q];
            gpre[q][0] = gi[0]; gpre[q][1] = gi[512]; gpre[q][2] = gi[1024];
            lp_r[q] = lp; valid_r[q] = valid;
        }

        // ---- per-warp poll: wait for H(t) published by all 64 blocks of this dir ----
        if (lane == 0) {
            unsigned tgt = 64u * (unsigned)(t + 1);
            volatile unsigned* p = &g_bar_ctr[d * 32];
            int bo = 4;
            while (*p < tgt) { __nanosleep(bo); if (bo < 32) bo += bo; }
            __threadfence();
        }
        __syncwarp();

        // ---- warp-private cp.async fill: rows [R0,R0+16) x K [kbase,kbase+256) ----
        const char* baseH = (const char*)(g_Hh[t & 1] + (size_t)d * 64 * 512);
        const char* baseL = (const char*)(g_Hl[t & 1] + (size_t)d * 64 * 512);
#pragma unroll
        for (int i0 = 0; i0 < 512; i0 += 32) {
            int i = i0 + lane;
            int rr = R0 + (i >> 5), seg = (i & 31) * 16;   // 16B segments
            unsigned dH = (unsigned)__cvta_generic_to_shared(Hsh + rr * 520 + kbase) + seg;
            unsigned dL = (unsigned)__cvta_generic_to_shared(Hsl + rr * 520 + kbase) + seg;
            const char* sH = baseH + (rr * 512 + kbase) * 2 + seg;
            const char* sL = baseL + (rr * 512 + kbase) * 2 + seg;
            asm volatile("cp.async.cg.shared.global [%0], [%1], 16;" :: "r"(dH), "l"(sH));
            asm volatile("cp.async.cg.shared.global [%0], [%1], 16;" :: "r"(dL), "l"(sL));
        }
        asm volatile("cp.async.commit_group;");
        float acc[3][4];
#pragma unroll
        for (int nt = 0; nt < 3; nt++)
#pragma unroll
            for (int q = 0; q < 4; q++) acc[nt][q] = 0.f;
        asm volatile("cp.async.wait_group 0;" ::: "memory");
        __syncwarp();

        // ---- warp's K-slice MMA ----
        mma_khalf(Hsh, Hsl, Wsh, Wsl, r, grp, qp2, kbase, kbase + 256, acc);

        // stage partial gh to smem [kh]
        float* gh_o = ghs + kh * (64 * 26);
#pragma unroll
        for (int nt = 0; nt < 3; nt++) {
            gh_o[r * 26 + nt * 8 + qp2]           = acc[nt][0];
            gh_o[r * 26 + nt * 8 + qp2 + 1]       = acc[nt][1];
            gh_o[(r + 8) * 26 + nt * 8 + qp2]     = acc[nt][2];
            gh_o[(r + 8) * 26 + nt * 8 + qp2 + 1] = acc[nt][3];
        }
        __syncthreads();

        // ---- gates + state update; publish H(t+1) to pong buffer ----
        float enc_r[2];
        __nv_bfloat16* outH = g_Hh[(t + 1) & 1] + (size_t)d * 64 * 512;
        __nv_bfloat16* outL = g_Hl[(t + 1) & 1] + (size_t)d * 64 * 512;
#pragma unroll
        for (int q = 0; q < 2; q++) {
            int sl = sl_r[q], jl = jl_r[q];
            float ghr = ghs[sl * 26 + jl]      + ghs[1664 + sl * 26 + jl]      + bhs[jl];
            float ghz = ghs[sl * 26 + 8 + jl]  + ghs[1664 + sl * 26 + 8 + jl]  + bhs[8 + jl];
            float ghn = ghs[sl * 26 + 16 + jl] + ghs[1664 + sl * 26 + 16 + jl] + bhs[16 + jl];
            float h = hloc[q];
            float rg = 1.f / (1.f + __expf(-(gpre[q][0] + ghr)));
            float zg = 1.f / (1.f + __expf(-(gpre[q][1] + ghz)));
            float ng = tanhf(gpre[q][2] + rg * ghn);
            float hnew = (1.f - zg) * ng + zg * h;
            float hout = valid_r[q] ? hnew : h;
            hloc[q] = hout;
            __nv_bfloat16 hi = __float2bfloat16(hout);
            outH[sl * 512 + j0 + jl] = hi;
            outL[sl * 512 + j0 + jl] = __float2bfloat16(hout - __bfloat162float(hi));
            enc_r[q] = valid_r[q] ? hnew : 0.f;
        }
        __syncthreads();
        if (tid == 0) { __threadfence(); atomicAdd(&g_bar_ctr[d * 32], 1u); }
        // ENC stores off the critical path
#pragma unroll
        for (int q = 0; q < 2; q++)
            g_ENC[((size_t)(sl_r[q] * 512 + lp_r[q])) * 1024 + d * 512 + j0 + jl_r[q]] = enc_r[q];
    }
}

// ---- K4: row norms ----
__global__ void norms_kernel() {
    int seq = blockIdx.x;
    int w = threadIdx.x >> 5, lane = threadIdx.x & 31;
    int i = blockIdx.y * 8 + w;
    const float* row = g_ENC + ((size_t)seq * 512 + i) * 1024;
    float sacc = 0.f;
    for (int k = lane; k < 1024; k += 32) { float v = row[k]; sacc += v * v; }
#pragma unroll
    for (int off = 16; off; off >>= 1) sacc += __shfl_down_sync(0xffffffffu, sacc, off);
    if (lane == 0) g_N[seq * 512 + i] = sqrtf(sacc);
}

// ---- K5: SIM via bf16-split mma.  Per batch: [512x1024] @ [512x1024]^T ----
__global__ __launch_bounds__(256) void sim_gemm_mma() {
    __shared__ __align__(16) __nv_bfloat16 Ah[128][40];
    __shared__ __align__(16) __nv_bfloat16 Al[128][40];
    __shared__ __align__(16) __nv_bfloat16 Bh[128][40];
    __shared__ __align__(16) __nv_bfloat16 Bl[128][40];
    int b = blockIdx.z;
    int n0 = blockIdx.x * 128, m0 = blockIdx.y * 128;
    int tid = threadIdx.x;
    int wid = tid >> 5, lane = tid & 31;
    int grp = lane >> 2, qp2 = (lane & 3) * 2;
    int wm = (wid >> 2) * 64, wn = (wid & 3) * 32;
    const float* A = g_ENC + ((size_t)b * 512 + m0) * 1024;
    const float* Bp = g_ENC + ((size_t)(32 + b) * 512 + n0) * 1024;
    float acc[4][4][4];
#pragma unroll
    for (int i = 0; i < 4; i++)
#pragma unroll
        for (int j = 0; j < 4; j++)
#pragma unroll
            for (int q = 0; q < 4; q++) acc[i][j][q] = 0.f;

    for (int c = 0; c < 32; c++) {
        int k0 = c * 32;
        __syncthreads();
#pragma unroll
        for (int p = 0; p < 4; p++) {
            int t2 = tid + p * 256;
            int row = t2 >> 3, c4 = (t2 & 7) * 4;
            float4 va = *(const float4*)(A + (size_t)row * 1024 + k0 + c4);
            float4 vb = *(const float4*)(Bp + (size_t)row * 1024 + k0 + c4);
            float ax = va.x, ay = va.y, az = va.z, aw = va.w;
            __nv_bfloat16 hx = __float2bfloat16(ax), hy = __float2bfloat16(ay);
            __nv_bfloat16 hz = __float2bfloat16(az), hw = __float2bfloat16(aw);
            *(uint32_t*)&Ah[row][c4]     = pack_bf2(ax, ay);
            *(uint32_t*)&Ah[row][c4 + 2] = pack_bf2(az, aw);
            *(uint32_t*)&Al[row][c4]     = pack_bf2(ax - __bfloat162float(hx), ay - __bfloat162float(hy));
            *(uint32_t*)&Al[row][c4 + 2] = pack_bf2(az - __bfloat162float(hz), aw - __bfloat162float(hw));
            float bxx = vb.x, byy = vb.y, bzz = vb.z, bww = vb.w;
            __nv_bfloat16 gx = __float2bfloat16(bxx), gy = __float2bfloat16(byy);
            __nv_bfloat16 gz = __float2bfloat16(bzz), gw = __float2bfloat16(bww);
            *(uint32_t*)&Bh[row][c4]     = pack_bf2(bxx, byy);
            *(uint32_t*)&Bh[row][c4 + 2] = pack_bf2(bzz, bww);
            *(uint32_t*)&Bl[row][c4]     = pack_bf2(bxx - __bfloat162float(gx), byy - __bfloat162float(gy));
            *(uint32_t*)&Bl[row][c4 + 2] = pack_bf2(bzz - __bfloat162float(gz), bww - __bfloat162float(gw));
        }
        __syncthreads();
#pragma unroll
        for (int kk = 0; kk < 32; kk += 16) {
            uint32_t ah[4][4], al[4][4];
#pragma unroll
            for (int i = 0; i < 4; i++) {
                int rr = wm + i * 16 + grp;
                ah[i][0] = *(uint32_t*)&Ah[rr][kk + qp2];
                ah[i][1] = *(uint32_t*)&Ah[rr + 8][kk + qp2];
                ah[i][2] = *(uint32_t*)&Ah[rr][kk + 8 + qp2];
                ah[i][3] = *(uint32_t*)&Ah[rr + 8][kk + 8 + qp2];
                al[i][0] = *(uint32_t*)&Al[rr][kk + qp2];
                al[i][1] = *(uint32_t*)&Al[rr + 8][kk + qp2];
                al[i][2] = *(uint32_t*)&Al[rr][kk + 8 + qp2];
                al[i][3] = *(uint32_t*)&Al[rr + 8][kk + 8 + qp2];
            }
#pragma unroll
            for (int j = 0; j < 4; j++) {
                int nr = wn + j * 8 + grp;
                uint32_t bh0 = *(uint32_t*)&Bh[nr][kk + qp2];
                uint32_t bh1 = *(uint32_t*)&Bh[nr][kk + 8 + qp2];
                uint32_t bl0 = *(uint32_t*)&Bl[nr][kk + qp2];
                uint32_t bl1 = *(uint32_t*)&Bl[nr][kk + 8 + qp2];
#pragma unroll
                for (int i = 0; i < 4; i++) {
                    MMA_BF16(acc[i][j], ah[i], bh0, bh1);
                    MMA_BF16(acc[i][j], ah[i], bl0, bl1);
                    MMA_BF16(acc[i][j], al[i], bh0, bh1);
                }
            }
        }
    }
#pragma unroll
    for (int i = 0; i < 4; i++) {
        int row0 = m0 + wm + i * 16 + grp;
        float n1a = g_N[b * 512 + row0];
        float n1b = g_N[b * 512 + row0 + 8];
#pragma unroll
        for (int j = 0; j < 4; j++) {
            int c0 = n0 + wn + j * 8 + qp2;
            float n2a = g_N[(32 + b) * 512 + c0];
            float n2b = g_N[(32 + b) * 512 + c0 + 1];
            float* d0 = g_SIM + ((size_t)b * 512 + row0) * 512 + c0;
            float* d1 = g_SIM + ((size_t)b * 512 + row0 + 8) * 512 + c0;
            d0[0] = acc[i][j][0] / fmaxf(n1a * n2a, 1e-8f);
            d0[1] = acc[i][j][1] / fmaxf(n1a * n2b, 1e-8f);
            d1[0] = acc[i][j][2] / fmaxf(n1b * n2a, 1e-8f);
            d1[1] = acc[i][j][3] / fmaxf(n1b * n2b, 1e-8f);
        }
    }
}

// ---- K6: max/argmax over axis 2 ----
__global__ void rowmax_kernel() {
    int b = blockIdx.x;
    int w = threadIdx.x >> 5, lane = threadIdx.x & 31;
    int i = blockIdx.y * 8 + w;
    const float* row = g_SIM + ((size_t)b * 512 + i) * 512;
    float best = -1e30f; int bi = 0;
    for (int j = lane; j < 512; j += 32) {
        float v = row[j];
        if (v > best) { best = v; bi = j; }
    }
#pragma unroll
    for (int off = 16; off; off >>= 1) {
        float v = __shfl_down_sync(0xffffffffu, best, off);
        int ii = __shfl_down_sync(0xffffffffu, bi, off);
        if (v > best || (v == best && ii < bi)) { best = v; bi = ii; }
    }
    if (lane == 0) {
        g_MS1[b * 512 + i] = best;
        g_RL1[b * 512 + i] = (float)(i - bi);
    }
}

// ---- K7: max/argmax over axis 1 ----
__global__ void colmax_kernel() {
    int b = blockIdx.x, j0 = blockIdx.y * 32;
    int g = threadIdx.x >> 5, j = threadIdx.x & 31;
    float best = -1e30f; int bi = 0;
    const float* S = g_SIM + (size_t)b * 512 * 512;
    for (int i = g; i < 512; i += 8) {
        float v = S[(size_t)i * 512 + j0 + j];
        if (v > best) { best = v; bi = i; }
    }
    __shared__ float sm[256];
    __shared__ int si[256];
    sm[threadIdx.x] = best; si[threadIdx.x] = bi;
    __syncthreads();
    if (g == 0) {
        for (int gg = 1; gg < 8; gg++) {
            float v = sm[gg * 32 + j]; int ii = si[gg * 32 + j];
            if (v > best || (v == best && ii < bi)) { best = v; bi = ii; }
        }
        int jj = j0 + j;
        g_MS2[b * 512 + jj] = best;
        g_RL2[b * 512 + jj] = (float)(jj - bi);
    }
}

// ---- K8: conv branches + BN + ReLU + maxpool ----
__global__ void branch_kernel(const float* __restrict__ cw0, const float* __restrict__ cw1,
                              const float* __restrict__ cw2, const float* __restrict__ cb,
                              const float* __restrict__ bng, const float* __restrict__ bnb,
                              const float* __restrict__ bnm, const float* __restrict__ bnv) {
    int b = blockIdx.x, br = blockIdx.y;
    __shared__ float xs[2][512];
    const float* ms = br ? g_MS2 : g_MS1;
    const float* rl = br ? g_RL2 : g_RL1;
    for (int i = threadIdx.x; i < 512; i += 384) {
        xs[0][i] = ms[b * 512 + i];
        xs[1][i] = rl[b * 512 + i];
    }
    __syncthreads();
    int t = threadIdx.x;
    int ci = t >> 7, o = t & 127;
    int ks = 2 + ci;
    const float* w = (ci == 0) ? cw0 : ((ci == 1) ? cw1 : cw2);
    float wreg[2][4];
    for (int c = 0; c < 2; c++)
        for (int q = 0; q < 4; q++) wreg[c][q] = (q < ks) ? w[(o * 2 + c) * ks + q] : 0.f;
    float bias = cb[ci * 128 + o];
    float inv = rsqrtf(bnv[ci * 128 + o] + 1e-5f);
    float sc = bng[ci * 128 + o] * inv;
    float sh = bnb[ci * 128 + o] + (bias - bnm[ci * 128 + o]) * sc;
    float best = -1e30f;
    int P = 512 - ks + 1;
    for (int p = 0; p < P; p++) {
        float v = 0.f;
        for (int q = 0; q < ks; q++) {
            v += wreg[0][q] * xs[0][p + q];
            v += wreg[1][q] * xs[1][p + q];
        }
        v = fmaxf(v * sc + sh, 0.f);
        best = fmaxf(best, v);
    }
    g_FEAT[b * 768 + br * 384 + ci * 128 + o] = best;
}

// ---- K9: fc + softmax ----
__global__ void fc_kernel(const float* __restrict__ fw, const float* __restrict__ fb,
                          float* __restrict__ out) {
    int b = blockIdx.x;
    int w = threadIdx.x >> 5, lane = threadIdx.x & 31;
    __shared__ float lg[2];
    if (w < 2) {
        float s = 0.f;
        for (int k = lane; k < 768; k += 32) s += fw[w * 768 + k] * g_FEAT[b * 768 + k];
#pragma unroll
        for (int off = 16; off; off >>= 1) s += __shfl_down_sync(0xffffffffu, s, off);
        if (lane == 0) lg[w] = s + fb[w];
    }
    __syncthreads();
    if (threadIdx.x == 0) {
        float m = fmaxf(lg[0], lg[1]);
        float e0 = expf(lg[0] - m), e1 = expf(lg[1] - m);
        float inv = 1.f / (e0 + e1);
        out[b * 2 + 0] = e0 * inv;
        out[b * 2 + 1] = e1 * inv;
    }
}

extern "C" void kernel_launch(void* const* d_in, const int* in_sizes, int n_in,
                              void* d_out, int out_size) {
    const int* word1 = (const int*)d_in[0];
    const int* word2 = (const int*)d_in[1];
    const int* piny1 = (const int*)d_in[2];
    const int* piny2 = (const int*)d_in[3];
    const int* len1  = (const int*)d_in[4];
    const int* len2  = (const int*)d_in[5];
    const int* tb1   = (const int*)d_in[6];
    const int* te1   = (const int*)d_in[7];
    const int* tb2   = (const int*)d_in[8];
    const int* te2   = (const int*)d_in[9];
    const float* ew  = (const float*)d_in[10];
    const float* ep  = (const float*)d_in[11];
    const float* pe  = (const float*)d_in[12];
    const float* wih = (const float*)d_in[13];
    const float* whh = (const float*)d_in[14];
    const float* bih = (const float*)d_in[15];
    const float* bhh = (const float*)d_in[16];
    const float* cw0 = (const float*)d_in[17];
    const float* cw1 = (const float*)d_in[18];
    const float* cw2 = (const float*)d_in[19];
    const float* cb  = (const float*)d_in[20];
    const float* bng = (const float*)d_in[21];
    const float* bnb = (const float*)d_in[22];
    const float* bnm = (const float*)d_in[23];
    const float* bnv = (const float*)d_in[24];
    const float* fw  = (const float*)d_in[25];
    const float* fb  = (const float*)d_in[26];
    float* out = (float*)d_out;

    const int GRU5_SMEM = (24*520*2 + 64*520*2) * 2 + 2*64*26*4 + 24*4;
    cudaFuncSetAttribute(gru_persist5, cudaFuncAttributeMaxDynamicSharedMemorySize, GRU5_SMEM);

    wconv<<<9984, 256>>>(wih);
    embed_pack<<<dim3(64, 512), 128>>>(word1, word2, piny1, piny2,
                                       tb1, te1, tb2, te2, ew, ep, pe);
    gemm_gi_mma<<<dim3(24, 256), 256>>>(bih);
    gru_persist5<<<128, 256, GRU5_SMEM>>>(whh, bhh, len1, len2);
    norms_kernel<<<dim3(64, 64), 256>>>();
    sim_gemm_mma<<<dim3(4, 4, 32), 256>>>();
    rowmax_kernel<<<dim3(32, 64), 256>>>();
    colmax_kernel<<<dim3(32, 16), 256>>>();
    branch_kernel<<<dim3(32, 2), 384>>>(cw0, cw1, cw2, cb, bng, bnb, bnm, bnv);
    fc_kernel<<<32, 64>>>(fw, fb, out);
}